// round 1
// baseline (speedup 1.0000x reference)
#include <cuda_runtime.h>
#include <math.h>

#define BB 4
#define CC 256
#define HH 64
#define WW 64
#define PP (HH*WW)
#define GG 4
#define CGRP 64

// ---------------- device scratch ----------------
__device__ float g_offset[BB*18*PP];        // offsets  [B][18][H][W]
__device__ float g_xdir  [BB*CC*PP];        // deform out
__device__ float g_xdense[BB*CC*PP];        // cross out
__device__ float g_a     [BB*64*PP];        // g1 out
__device__ float g_attn  [BB*CC*PP];        // g2 out
__device__ float g_wdt   [9*GG*CGRP*CGRP];  // w_def transposed: [k][g][cg][co]
__device__ float g_w1t   [CC*64*9];         // w_g1 transposed:  [ci][co*9+k]

__device__ __forceinline__ float sigm(float v){ return 1.0f/(1.0f+expf(-v)); }

// ---------------- weight transposes ----------------
__global__ void transpose_wdef(const float* __restrict__ w_def){
    int id = blockIdx.x*256 + threadIdx.x;
    if (id >= 9*GG*CGRP*CGRP) return;
    int co = id & 63;
    int r  = id >> 6;
    int cg = r & 63;
    int kg = r >> 6;          // k*4 + g
    int k  = kg >> 2;
    int g  = kg & 3;
    g_wdt[id] = w_def[ ((g*CGRP + co)*CGRP + cg)*9 + k ];
}

__global__ void transpose_wg1(const float* __restrict__ w_g1){
    int id = blockIdx.x*256 + threadIdx.x;
    if (id >= CC*64*9) return;
    int e  = id % 576;
    int ci = id / 576;
    int co = e / 9;
    int k  = e % 9;
    g_w1t[id] = w_g1[(co*CC + ci)*9 + k];
}

// ---------------- offset conv: 3x3, 256 -> 18, pad=1, bias ----------------
__global__ __launch_bounds__(128) void offset_conv(const float* __restrict__ x,
                                                   const float* __restrict__ w_off,
                                                   const float* __restrict__ b_off){
    __shared__ float xr[3][66];
    __shared__ float ws[18][9];
    int b = blockIdx.x >> 6;
    int y = blockIdx.x & 63;
    int t = threadIdx.x;       // 128
    int pix  = t & 63;
    int half = t >> 6;         // 0/1 -> 9 co each
    float acc[9];
    #pragma unroll
    for (int q=0;q<9;q++) acc[q]=0.f;

    for (int ci=0; ci<CC; ci++){
        for (int e=t; e<198; e+=128){
            int r = e/66, xx = e - r*66;
            int row = y - 1 + r, col = xx - 1;
            float v = 0.f;
            if (row>=0 && row<HH && col>=0 && col<WW)
                v = x[((b*CC+ci)*HH + row)*WW + col];
            xr[r][xx] = v;
        }
        for (int e=t; e<162; e+=128){
            int co = e/9, k = e - co*9;
            ws[co][k] = w_off[(co*CC + ci)*9 + k];
        }
        __syncthreads();
        float win[3][3];
        #pragma unroll
        for (int r=0;r<3;r++)
            #pragma unroll
            for (int s=0;s<3;s++) win[r][s] = xr[r][pix+s];
        #pragma unroll
        for (int q=0;q<9;q++){
            int co = half*9+q;
            float s0=0.f;
            #pragma unroll
            for (int r=0;r<3;r++)
                #pragma unroll
                for (int s=0;s<3;s++) s0 += ws[co][r*3+s]*win[r][s];
            acc[q] += s0;
        }
        __syncthreads();
    }
    #pragma unroll
    for (int q=0;q<9;q++){
        int co = half*9+q;
        g_offset[((b*18+co)*HH + y)*WW + pix] = acc[q] + b_off[co];
    }
}

// ---------------- deformable conv ----------------
// block: (b, g, row y). 64 pixels x 64 out-ch per group. samples shared in smem.
__global__ __launch_bounds__(256) void deform_conv(const float* __restrict__ x,
                                                   const float* __restrict__ /*unused*/ wdummy){
    __shared__ int   s_iy[9][64];
    __shared__ int   s_ix[9][64];
    __shared__ float s_fy[9][64];
    __shared__ float s_fx[9][64];
    __shared__ __align__(16) float s_w[64][64];   // [cg][co]
    __shared__ __align__(16) float s_s[64][64];   // [cg][pix]

    int y = blockIdx.x;
    int g = blockIdx.y;
    int b = blockIdx.z;
    int t = threadIdx.x;

    // coords
    for (int e=t; e<576; e+=256){
        int k = e >> 6, pix = e & 63;
        float dy = g_offset[((b*18 + 2*k  )*HH + y)*WW + pix];
        float dx = g_offset[((b*18 + 2*k+1)*HH + y)*WW + pix];
        float py = (float)y   + (float)(k/3 - 1) + dy;
        float px = (float)pix + (float)(k%3 - 1) + dx;
        float fy = floorf(py), fx = floorf(px);
        s_iy[k][pix] = (int)fy;
        s_ix[k][pix] = (int)fx;
        s_fy[k][pix] = py - fy;
        s_fx[k][pix] = px - fx;
    }
    __syncthreads();

    int co_l = (t >> 4) << 2;   // 0..60 step 4
    int pp   = (t & 15) << 2;   // 0..60 step 4
    int pix  = t & 63;
    int cq   = t >> 6;          // 0..3 (16 cg each)

    float acc[4][4];
    #pragma unroll
    for (int i=0;i<4;i++)
        #pragma unroll
        for (int j=0;j<4;j++) acc[i][j]=0.f;

    const float* xb = x + (size_t)(b*CC + g*CGRP)*PP;

    for (int k=0;k<9;k++){
        // weights [cg][co] (coalesced via g_wdt)
        {
            int base = ((k*GG + g)*CGRP)*CGRP;
            float* sw = &s_w[0][0];
            for (int e=t; e<4096; e+=256) sw[e] = g_wdt[base + e];
        }
        // samples
        {
            int y0 = s_iy[k][pix], x0 = s_ix[k][pix];
            float wy = s_fy[k][pix], wx = s_fx[k][pix];
            float w00 = (1.f-wy)*(1.f-wx);
            float w01 = (1.f-wy)*wx;
            float w10 = wy*(1.f-wx);
            float w11 = wy*wx;
            bool vy0 = (y0 >= 0) && (y0 < HH);
            bool vy1 = (y0 >= -1) && (y0 < HH-1);
            bool vx0 = (x0 >= 0) && (x0 < WW);
            bool vx1 = (x0 >= -1) && (x0 < WW-1);
            float m00 = (vy0 && vx0) ? w00 : 0.f;
            float m01 = (vy0 && vx1) ? w01 : 0.f;
            float m10 = (vy1 && vx0) ? w10 : 0.f;
            float m11 = (vy1 && vx1) ? w11 : 0.f;
            int cy0 = min(max(y0,0),HH-1), cy1 = min(max(y0+1,0),HH-1);
            int cx0 = min(max(x0,0),WW-1), cx1 = min(max(x0+1,0),WW-1);
            int i00 = cy0*WW+cx0, i01 = cy0*WW+cx1;
            int i10 = cy1*WW+cx0, i11 = cy1*WW+cx1;
            #pragma unroll 4
            for (int j=0;j<16;j++){
                int cg = cq*16 + j;
                const float* p = xb + (size_t)cg*PP;
                float v = p[i00]*m00 + p[i01]*m01 + p[i10]*m10 + p[i11]*m11;
                s_s[cg][pix] = v;
            }
        }
        __syncthreads();
        // 64x64 outer-product accumulate
        #pragma unroll 16
        for (int cg=0; cg<64; cg++){
            float4 sv = *(const float4*)&s_s[cg][pp];
            float4 wv = *(const float4*)&s_w[cg][co_l];
            acc[0][0] += wv.x*sv.x; acc[0][1] += wv.x*sv.y; acc[0][2] += wv.x*sv.z; acc[0][3] += wv.x*sv.w;
            acc[1][0] += wv.y*sv.x; acc[1][1] += wv.y*sv.y; acc[1][2] += wv.y*sv.z; acc[1][3] += wv.y*sv.w;
            acc[2][0] += wv.z*sv.x; acc[2][1] += wv.z*sv.y; acc[2][2] += wv.z*sv.z; acc[2][3] += wv.z*sv.w;
            acc[3][0] += wv.w*sv.x; acc[3][1] += wv.w*sv.y; acc[3][2] += wv.w*sv.z; acc[3][3] += wv.w*sv.w;
        }
        __syncthreads();
    }

    #pragma unroll
    for (int i=0;i<4;i++){
        int co = g*CGRP + co_l + i;
        float4 v = make_float4(acc[i][0], acc[i][1], acc[i][2], acc[i][3]);
        *(float4*)&g_xdir[(size_t)(b*CC + co)*PP + y*WW + pp] = v;
    }
}

// ---------------- generic 1x1 GEMM (Co=256) ----------------
// MODE 0: cross (in = concat(g_xdir, x_prev), CIN=512) -> g_xdense
// MODE 1: g2    (in = g_a, CIN=64, bias+sigmoid)       -> g_attn
// MODE 2: out   (in = g_xdense*g_attn, CIN=256, bias+bn+silu+resid) -> out
template<int CIN, int MODE>
__global__ __launch_bounds__(256) void gemm1x1(const float* __restrict__ Wt,
                                               const float* __restrict__ xprev,
                                               const float* __restrict__ bias,
                                               const float* __restrict__ gamma,
                                               const float* __restrict__ beta,
                                               const float* __restrict__ mean,
                                               const float* __restrict__ var,
                                               const float* __restrict__ resid,
                                               float* __restrict__ outp){
    __shared__ __align__(16) float As[16][64];
    __shared__ __align__(16) float Bs[16][64];

    int p0  = blockIdx.x * 64;
    int co0 = blockIdx.y * 64;
    int b   = blockIdx.z;
    int t   = threadIdx.x;
    int co_l = (t >> 4) << 2;
    int pp   = (t & 15) << 2;

    float acc[4][4];
    #pragma unroll
    for (int i=0;i<4;i++)
        #pragma unroll
        for (int j=0;j<4;j++) acc[i][j]=0.f;

    for (int k0=0; k0<CIN; k0+=16){
        #pragma unroll
        for (int r=0;r<4;r++){
            int e = t + r*256;
            { // A: weights
                int ci_i = e & 15, co_i = e >> 4;
                As[ci_i][co_i] = Wt[(size_t)(co0+co_i)*CIN + k0 + ci_i];
            }
            { // B: inputs
                int p_i = e & 63, ci_i = e >> 6;  // 0..15
                int ci = k0 + ci_i;
                float v;
                if (MODE == 0){
                    if (ci < CC) v = g_xdir [(size_t)(b*CC+ci)*PP + p0 + p_i];
                    else         v = xprev  [(size_t)(b*CC+(ci-CC))*PP + p0 + p_i];
                } else if (MODE == 1){
                    v = g_a[(size_t)(b*64+ci)*PP + p0 + p_i];
                } else {
                    size_t idx = (size_t)(b*CC+ci)*PP + p0 + p_i;
                    v = g_xdense[idx] * g_attn[idx];
                }
                Bs[ci_i][p_i] = v;
            }
        }
        __syncthreads();
        #pragma unroll
        for (int kk=0;kk<16;kk++){
            float4 a4 = *(const float4*)&As[kk][co_l];
            float4 b4 = *(const float4*)&Bs[kk][pp];
            acc[0][0] += a4.x*b4.x; acc[0][1] += a4.x*b4.y; acc[0][2] += a4.x*b4.z; acc[0][3] += a4.x*b4.w;
            acc[1][0] += a4.y*b4.x; acc[1][1] += a4.y*b4.y; acc[1][2] += a4.y*b4.z; acc[1][3] += a4.y*b4.w;
            acc[2][0] += a4.z*b4.x; acc[2][1] += a4.z*b4.y; acc[2][2] += a4.z*b4.z; acc[2][3] += a4.z*b4.w;
            acc[3][0] += a4.w*b4.x; acc[3][1] += a4.w*b4.y; acc[3][2] += a4.w*b4.z; acc[3][3] += a4.w*b4.w;
        }
        __syncthreads();
    }

    #pragma unroll
    for (int i=0;i<4;i++){
        int co = co0 + co_l + i;
        size_t base = (size_t)(b*CC + co)*PP + p0 + pp;
        if (MODE == 0){
            float4 v = make_float4(acc[i][0],acc[i][1],acc[i][2],acc[i][3]);
            *(float4*)&g_xdense[base] = v;
        } else if (MODE == 1){
            float bb = bias[co];
            float4 v = make_float4(sigm(acc[i][0]+bb), sigm(acc[i][1]+bb),
                                   sigm(acc[i][2]+bb), sigm(acc[i][3]+bb));
            *(float4*)&g_attn[base] = v;
        } else {
            float bb  = bias[co];
            float inv = gamma[co] * rsqrtf(var[co] + 1e-5f);
            float sh  = beta[co] - mean[co]*inv;
            float4 rv = *(const float4*)&resid[base];
            float o0,o1,o2,o3;
            { float v = (acc[i][0]+bb)*inv + sh; o0 = rv.x + v*sigm(v); }
            { float v = (acc[i][1]+bb)*inv + sh; o1 = rv.y + v*sigm(v); }
            { float v = (acc[i][2]+bb)*inv + sh; o2 = rv.z + v*sigm(v); }
            { float v = (acc[i][3]+bb)*inv + sh; o3 = rv.w + v*sigm(v); }
            *(float4*)&outp[base] = make_float4(o0,o1,o2,o3);
        }
    }
}

// ---------------- g1 conv: 3x3, 256 -> 64, pad=1, bias+bn+silu ----------------
__global__ __launch_bounds__(256) void g1_conv(const float* __restrict__ b_g1,
                                               const float* __restrict__ gamma,
                                               const float* __restrict__ beta,
                                               const float* __restrict__ mean,
                                               const float* __restrict__ var){
    __shared__ float xr[3][66];
    __shared__ float ws[576];
    int b = blockIdx.x >> 6;
    int y = blockIdx.x & 63;
    int t = threadIdx.x;
    int co_l = (t >> 4) << 2;
    int pp   = (t & 15) << 2;

    float acc[4][4];
    #pragma unroll
    for (int i=0;i<4;i++)
        #pragma unroll
        for (int j=0;j<4;j++) acc[i][j]=0.f;

    for (int ci=0; ci<CC; ci++){
        for (int e=t; e<198; e+=256){
            int r = e/66, xx = e - r*66;
            int row = y - 1 + r, col = xx - 1;
            float v = 0.f;
            if (row>=0 && row<HH && col>=0 && col<WW)
                v = g_xdense[((size_t)(b*CC+ci)*HH + row)*WW + col];
            xr[r][xx] = v;
        }
        for (int e=t; e<576; e+=256) ws[e] = g_w1t[ci*576 + e];
        __syncthreads();
        float win[3][6];
        #pragma unroll
        for (int r=0;r<3;r++)
            #pragma unroll
            for (int u=0;u<6;u++) win[r][u] = xr[r][pp+u];
        #pragma unroll
        for (int i=0;i<4;i++){
            #pragma unroll
            for (int kk=0;kk<9;kk++){
                float wv = ws[(co_l+i)*9 + kk];
                int r = kk/3, s = kk%3;
                #pragma unroll
                for (int j=0;j<4;j++) acc[i][j] += wv * win[r][s+j];
            }
        }
        __syncthreads();
    }

    #pragma unroll
    for (int i=0;i<4;i++){
        int co = co_l + i;
        float bb  = b_g1[co];
        float inv = gamma[co] * rsqrtf(var[co] + 1e-5f);
        float sh  = beta[co] - mean[co]*inv;
        float4 o;
        { float v = (acc[i][0]+bb)*inv + sh; o.x = v*sigm(v); }
        { float v = (acc[i][1]+bb)*inv + sh; o.y = v*sigm(v); }
        { float v = (acc[i][2]+bb)*inv + sh; o.z = v*sigm(v); }
        { float v = (acc[i][3]+bb)*inv + sh; o.w = v*sigm(v); }
        *(float4*)&g_a[(size_t)(b*64 + co)*PP + y*WW + pp] = o;
    }
}

// ---------------- launch ----------------
extern "C" void kernel_launch(void* const* d_in, const int* in_sizes, int n_in,
                              void* d_out, int out_size){
    const float* x       = (const float*)d_in[0];
    const float* x_prev  = (const float*)d_in[1];
    const float* w_off   = (const float*)d_in[2];
    const float* b_off   = (const float*)d_in[3];
    const float* w_def   = (const float*)d_in[4];
    const float* w_cross = (const float*)d_in[5];
    const float* w_g1    = (const float*)d_in[6];
    const float* b_g1    = (const float*)d_in[7];
    const float* g1_gamma= (const float*)d_in[8];
    const float* g1_beta = (const float*)d_in[9];
    const float* g1_mean = (const float*)d_in[10];
    const float* g1_var  = (const float*)d_in[11];
    const float* w_g2    = (const float*)d_in[12];
    const float* b_g2    = (const float*)d_in[13];
    const float* w_out   = (const float*)d_in[14];
    const float* b_out   = (const float*)d_in[15];
    const float* o_gamma = (const float*)d_in[16];
    const float* o_beta  = (const float*)d_in[17];
    const float* o_mean  = (const float*)d_in[18];
    const float* o_var   = (const float*)d_in[19];
    float* out = (float*)d_out;

    transpose_wdef<<<576, 256>>>(w_def);
    transpose_wg1 <<<576, 256>>>(w_g1);
    offset_conv<<<BB*HH, 128>>>(x, w_off, b_off);
    deform_conv<<<dim3(HH, GG, BB), 256>>>(x, nullptr);
    gemm1x1<512,0><<<dim3(PP/64, CC/64, BB), 256>>>(w_cross, x_prev,
        nullptr, nullptr, nullptr, nullptr, nullptr, nullptr, nullptr);
    g1_conv<<<BB*HH, 256>>>(b_g1, g1_gamma, g1_beta, g1_mean, g1_var);
    gemm1x1<64,1><<<dim3(PP/64, CC/64, BB), 256>>>(w_g2, nullptr,
        b_g2, nullptr, nullptr, nullptr, nullptr, nullptr, nullptr);
    gemm1x1<256,2><<<dim3(PP/64, CC/64, BB), 256>>>(w_out, nullptr,
        b_out, o_gamma, o_beta, o_mean, o_var, x, out);
}

// round 3
// speedup vs baseline: 1.5755x; 1.5755x over previous
#include <cuda_runtime.h>
#include <cuda_bf16.h>
#include <math.h>
#include <stdint.h>

#define BB 4
#define CC 256
#define HH 64
#define WW 64
#define PP (HH*WW)
#define GG 4
#define CGRP 64

// ---------------- device scratch ----------------
__device__ float g_offset[BB*18*PP];
__device__ float g_xdir  [BB*CC*PP];
__device__ float g_xdense[BB*CC*PP];
__device__ float g_a     [BB*64*PP];
__device__ float g_attn  [BB*CC*PP];
__device__ float g_wdt   [9*GG*CGRP*CGRP];
__device__ float g_w1t   [CC*64*9];

// bf16 hi/lo operands for tensor-core GEMMs
__device__ __nv_bfloat16 g_Achi[256*512], g_Aclo[256*512];
__device__ __nv_bfloat16 g_Ag2hi[256*64], g_Ag2lo[256*64];
__device__ __nv_bfloat16 g_Aohi[256*256], g_Aolo[256*256];
__device__ __nv_bfloat16 g_Bchi[(size_t)BB*PP*512], g_Bclo[(size_t)BB*PP*512];
__device__ __nv_bfloat16 g_Bahi[(size_t)BB*PP*64],  g_Balo[(size_t)BB*PP*64];
__device__ __nv_bfloat16 g_Bohi[(size_t)BB*PP*256], g_Bolo[(size_t)BB*PP*256];

__device__ __forceinline__ float sigm(float v){ return 1.0f/(1.0f+expf(-v)); }

__device__ __forceinline__ uint32_t smem_u32(const void* p){
    uint32_t a;
    asm("{ .reg .u64 tmp; cvta.to.shared.u64 tmp, %1; cvt.u32.u64 %0, tmp; }" : "=r"(a) : "l"(p));
    return a;
}

#define LDSM_X4(r, addr) \
    asm volatile("ldmatrix.sync.aligned.m8n8.x4.shared.b16 {%0,%1,%2,%3}, [%4];" \
        : "=r"((r)[0]), "=r"((r)[1]), "=r"((r)[2]), "=r"((r)[3]) : "r"(addr))
#define LDSM_X2(r, addr) \
    asm volatile("ldmatrix.sync.aligned.m8n8.x2.shared.b16 {%0,%1}, [%2];" \
        : "=r"((r)[0]), "=r"((r)[1]) : "r"(addr))
#define MMA16816(d, a, bfr) \
    asm volatile("mma.sync.aligned.m16n8k16.row.col.f32.bf16.bf16.f32 " \
        "{%0,%1,%2,%3}, {%4,%5,%6,%7}, {%8,%9}, {%0,%1,%2,%3};" \
        : "+f"((d)[0]), "+f"((d)[1]), "+f"((d)[2]), "+f"((d)[3]) \
        : "r"((a)[0]), "r"((a)[1]), "r"((a)[2]), "r"((a)[3]), "r"((bfr)[0]), "r"((bfr)[1]))

// ---------------- weight transposes ----------------
__global__ void transpose_wdef(const float* __restrict__ w_def){
    int id = blockIdx.x*256 + threadIdx.x;
    if (id >= 9*GG*CGRP*CGRP) return;
    int co = id & 63;
    int r  = id >> 6;
    int cg = r & 63;
    int kg = r >> 6;
    int k  = kg >> 2;
    int g  = kg & 3;
    g_wdt[id] = w_def[ ((g*CGRP + co)*CGRP + cg)*9 + k ];
}

__global__ void transpose_wg1(const float* __restrict__ w_g1){
    int id = blockIdx.x*256 + threadIdx.x;
    if (id >= CC*64*9) return;
    int e  = id % 576;
    int ci = id / 576;
    int co = e / 9;
    int k  = e % 9;
    g_w1t[id] = w_g1[(co*CC + ci)*9 + k];
}

// ---------------- weight hi/lo split ----------------
template<int WSEL>
__global__ void split_w(const float* __restrict__ src, int n){
    int i = blockIdx.x*256 + threadIdx.x;
    if (i >= n) return;
    float v = src[i];
    __nv_bfloat16 h = __float2bfloat16(v);
    __nv_bfloat16 l = __float2bfloat16(v - __bfloat162float(h));
    if (WSEL==0){ g_Achi[i]=h;  g_Aclo[i]=l;  }
    if (WSEL==1){ g_Ag2hi[i]=h; g_Ag2lo[i]=l; }
    if (WSEL==2){ g_Aohi[i]=h;  g_Aolo[i]=l;  }
}

// ---------------- transpose+split converters: [ch][px] -> [px][ch] hi/lo ----------------
template<int CH, int SRC>
__global__ __launch_bounds__(256) void trans_split(const float* __restrict__ xprev){
    __shared__ float tile[32][33];
    int px0 = blockIdx.x*32;
    int ch0 = blockIdx.y*32;
    int b   = blockIdx.z;
    int t   = threadIdx.x;
    #pragma unroll
    for (int i=0;i<4;i++){
        int e = t + i*256;
        int r = e >> 5, c = e & 31;       // r = ch_local, c = px_local
        int ch = ch0 + r;
        float v;
        if (SRC==0){
            if (ch < 256) v = g_xdir[((size_t)(b*256+ch))*PP + px0 + c];
            else          v = xprev [((size_t)(b*256+ch-256))*PP + px0 + c];
        } else if (SRC==1){
            v = g_a[((size_t)(b*64+ch))*PP + px0 + c];
        } else {
            size_t idx = ((size_t)(b*256+ch))*PP + px0 + c;
            v = g_xdense[idx] * g_attn[idx];
        }
        tile[r][c] = v;
    }
    __syncthreads();
    #pragma unroll
    for (int i=0;i<4;i++){
        int e = t + i*256;
        int r = e >> 5, c = e & 31;       // r = px_local, c = ch_local
        float v = tile[c][r];
        __nv_bfloat16 h = __float2bfloat16(v);
        __nv_bfloat16 l = __float2bfloat16(v - __bfloat162float(h));
        size_t o = ((size_t)(b*PP) + px0 + r)*CH + ch0 + c;
        if (SRC==0){ g_Bchi[o]=h; g_Bclo[o]=l; }
        if (SRC==1){ g_Bahi[o]=h; g_Balo[o]=l; }
        if (SRC==2){ g_Bohi[o]=h; g_Bolo[o]=l; }
    }
}

// ---------------- mma.sync GEMM: 128co x 128px block, 8 warps (2x4), K-chunks 64 ----------
// D[co][px] = sum_k A[co][k]*B[px][k], 3-term hi/lo bf16 split.
// smem tiles: stride 72 bf16 (144 B = 16-aligned, ldmatrix conflict-free)
#define T_STRIDE 72
#define T_BYTES  (128*T_STRIDE*2)       // 18432
#define SMEM_GEMM (4*T_BYTES)           // 73728

__device__ __forceinline__ void fill72(char* dst, const __nv_bfloat16* __restrict__ src,
                                       int ldk, int t){
    #pragma unroll
    for (int i=0;i<4;i++){
        int e = t + i*256;          // 0..1023
        int r = e >> 3, c = e & 7;  // 128 rows x 8 x (8 bf16)
        uint4 v = *(const uint4*)(src + (size_t)r*ldk + c*8);
        *(uint4*)(dst + r*144 + c*16) = v;
    }
}

template<int MODE>
__global__ __launch_bounds__(256) void gemm_mma(const float* __restrict__ bias,
                                                const float* __restrict__ gamma,
                                                const float* __restrict__ beta,
                                                const float* __restrict__ mean,
                                                const float* __restrict__ var,
                                                const float* __restrict__ resid,
                                                float* __restrict__ outp){
    constexpr int K = (MODE==0) ? 512 : (MODE==1 ? 64 : 256);
    constexpr int CHUNKS = K/64;
    extern __shared__ char smem[];
    uint32_t su = smem_u32(smem);
    int t    = threadIdx.x;
    int lane = t & 31;
    int wid  = t >> 5;
    int wm   = wid >> 2;   // 0..1
    int wn   = wid & 3;    // 0..3
    int px0  = blockIdx.x*128;
    int co0  = blockIdx.y*128;
    int b    = blockIdx.z;

    const __nv_bfloat16* Ahi = (MODE==0) ? g_Achi : (MODE==1 ? g_Ag2hi : g_Aohi);
    const __nv_bfloat16* Alo = (MODE==0) ? g_Aclo : (MODE==1 ? g_Ag2lo : g_Aolo);
    const __nv_bfloat16* Bhi = (MODE==0) ? g_Bchi : (MODE==1 ? g_Bahi : g_Bohi);
    const __nv_bfloat16* Blo = (MODE==0) ? g_Bclo : (MODE==1 ? g_Balo : g_Bolo);

    const __nv_bfloat16* Ab  = Ahi + (size_t)co0*K;
    const __nv_bfloat16* Alb = Alo + (size_t)co0*K;
    const __nv_bfloat16* Bb  = Bhi + ((size_t)(b*PP) + px0)*K;
    const __nv_bfloat16* Blb = Blo + ((size_t)(b*PP) + px0)*K;

    float acc[4][4][4];
    #pragma unroll
    for (int i=0;i<4;i++)
        #pragma unroll
        for (int j=0;j<4;j++)
            #pragma unroll
            for (int q=0;q<4;q++) acc[i][j][q] = 0.f;

    int l16 = lane & 15;
    // ldmatrix source offsets (bytes) within a tile
    uint32_t aoff_base = (uint32_t)((wm*64 + (lane & 15))*144 + ((lane >> 4) << 3)*2);
    uint32_t boff_base = (uint32_t)((wn*32 + (l16 & 7))*144 + ((l16 >> 3) << 3)*2);

    for (int c = 0; c < CHUNKS; c++){
        if (c) __syncthreads();
        fill72(smem,             Ab  + c*64, K, t);
        fill72(smem +   T_BYTES, Alb + c*64, K, t);
        fill72(smem + 2*T_BYTES, Bb  + c*64, K, t);
        fill72(smem + 3*T_BYTES, Blb + c*64, K, t);
        __syncthreads();
        #pragma unroll
        for (int ks = 0; ks < 4; ks++){
            uint32_t bh[4][2], bl[4][2];
            #pragma unroll
            for (int na=0;na<4;na++){
                uint32_t boff = boff_base + (uint32_t)(na*8*144 + ks*32);
                LDSM_X2(bh[na], su + 2*T_BYTES + boff);
                LDSM_X2(bl[na], su + 3*T_BYTES + boff);
            }
            #pragma unroll
            for (int ma=0;ma<4;ma++){
                uint32_t aoff = aoff_base + (uint32_t)(ma*16*144 + ks*32);
                uint32_t ah[4], al[4];
                LDSM_X4(ah, su + aoff);
                LDSM_X4(al, su + T_BYTES + aoff);
                #pragma unroll
                for (int na=0;na<4;na++){
                    MMA16816(acc[ma][na], ah, bh[na]);
                    MMA16816(acc[ma][na], al, bh[na]);
                    MMA16816(acc[ma][na], ah, bl[na]);
                }
            }
        }
    }

    // epilogue
    #pragma unroll
    for (int ma=0;ma<4;ma++){
        int r0 = co0 + wm*64 + ma*16 + (lane>>2);
        int r1 = r0 + 8;
        float bb0=0.f,bb1=0.f,iv0=0.f,iv1=0.f,sh0=0.f,sh1=0.f;
        if (MODE==1){ bb0 = bias[r0]; bb1 = bias[r1]; }
        if (MODE==2){
            bb0 = bias[r0]; bb1 = bias[r1];
            iv0 = gamma[r0]*rsqrtf(var[r0]+1e-5f); sh0 = beta[r0]-mean[r0]*iv0;
            iv1 = gamma[r1]*rsqrtf(var[r1]+1e-5f); sh1 = beta[r1]-mean[r1]*iv1;
        }
        #pragma unroll
        for (int na=0;na<4;na++){
            int px = px0 + wn*32 + na*8 + ((lane&3)<<1);
            size_t i0 = ((size_t)(b*CC + r0))*PP + px;
            size_t i1 = ((size_t)(b*CC + r1))*PP + px;
            float d0 = acc[ma][na][0], d1 = acc[ma][na][1];
            float d2 = acc[ma][na][2], d3 = acc[ma][na][3];
            if (MODE==0){
                *(float2*)&g_xdense[i0] = make_float2(d0, d1);
                *(float2*)&g_xdense[i1] = make_float2(d2, d3);
            } else if (MODE==1){
                *(float2*)&g_attn[i0] = make_float2(sigm(d0+bb0), sigm(d1+bb0));
                *(float2*)&g_attn[i1] = make_float2(sigm(d2+bb1), sigm(d3+bb1));
            } else {
                float2 rv0 = *(const float2*)&resid[i0];
                float2 rv1 = *(const float2*)&resid[i1];
                float v0 = (d0+bb0)*iv0 + sh0;
                float v1 = (d1+bb0)*iv0 + sh0;
                float v2 = (d2+bb1)*iv1 + sh1;
                float v3 = (d3+bb1)*iv1 + sh1;
                *(float2*)&outp[i0] = make_float2(rv0.x + v0*sigm(v0), rv0.y + v1*sigm(v1));
                *(float2*)&outp[i1] = make_float2(rv1.x + v2*sigm(v2), rv1.y + v3*sigm(v3));
            }
        }
    }
}

// ---------------- offset conv: 3x3, 256->18, pad=1, bias (ci-chunked) ----------------
__global__ __launch_bounds__(256) void offset_conv2(const float* __restrict__ x,
                                                    const float* __restrict__ w_off,
                                                    const float* __restrict__ b_off){
    __shared__ float xr[8][4][66];
    __shared__ float ws[8][18][9];
    int b  = blockIdx.x >> 5;
    int yp = blockIdx.x & 31;
    int y0 = yp*2;
    int t  = threadIdx.x;
    int row  = t >> 7;
    int pix  = t & 63;
    int half = (t >> 6) & 1;
    float acc[9];
    #pragma unroll
    for (int q=0;q<9;q++) acc[q]=0.f;

    for (int c0=0; c0<CC; c0+=8){
        for (int e=t; e<2112; e+=256){
            int ci = e/264; int rem = e - ci*264;
            int rr = rem/66; int xx = rem - rr*66;
            int yy = y0 - 1 + rr, col = xx - 1;
            float v = 0.f;
            if (yy>=0 && yy<HH && col>=0 && col<WW)
                v = x[((b*CC + c0 + ci)*HH + yy)*WW + col];
            xr[ci][rr][xx] = v;
        }
        for (int e=t; e<1296; e+=256){
            int ci = e/162; int rem = e - ci*162;
            int co = rem/9; int k = rem - co*9;
            ws[ci][co][k] = w_off[(co*CC + c0 + ci)*9 + k];
        }
        __syncthreads();
        #pragma unroll
        for (int ci=0; ci<8; ci++){
            float win[3][3];
            #pragma unroll
            for (int r=0;r<3;r++)
                #pragma unroll
                for (int s=0;s<3;s++) win[r][s] = xr[ci][row+r][pix+s];
            #pragma unroll
            for (int q=0;q<9;q++){
                int co = half*9+q;
                float s0 = 0.f;
                #pragma unroll
                for (int r=0;r<3;r++)
                    #pragma unroll
                    for (int s=0;s<3;s++) s0 += ws[ci][co][r*3+s]*win[r][s];
                acc[q] += s0;
            }
        }
        __syncthreads();
    }
    #pragma unroll
    for (int q=0;q<9;q++){
        int co = half*9+q;
        g_offset[((b*18+co)*HH + y0+row)*WW + pix] = acc[q] + b_off[co];
    }
}

// ---------------- deformable conv ----------------
__global__ __launch_bounds__(256) void deform_conv(const float* __restrict__ x,
                                                   const float* __restrict__ wdummy){
    __shared__ int   s_iy[9][64];
    __shared__ int   s_ix[9][64];
    __shared__ float s_fy[9][64];
    __shared__ float s_fx[9][64];
    __shared__ __align__(16) float s_w[64][64];
    __shared__ __align__(16) float s_s[64][64];

    int y = blockIdx.x;
    int g = blockIdx.y;
    int b = blockIdx.z;
    int t = threadIdx.x;

    for (int e=t; e<576; e+=256){
        int k = e >> 6, pix = e & 63;
        float dy = g_offset[((b*18 + 2*k  )*HH + y)*WW + pix];
        float dx = g_offset[((b*18 + 2*k+1)*HH + y)*WW + pix];
        float py = (float)y   + (float)(k/3 - 1) + dy;
        float px = (float)pix + (float)(k%3 - 1) + dx;
        float fy = floorf(py), fx = floorf(px);
        s_iy[k][pix] = (int)fy;
        s_ix[k][pix] = (int)fx;
        s_fy[k][pix] = py - fy;
        s_fx[k][pix] = px - fx;
    }
    __syncthreads();

    int co_l = (t >> 4) << 2;
    int pp   = (t & 15) << 2;
    int pix  = t & 63;
    int cq   = t >> 6;

    float acc[4][4];
    #pragma unroll
    for (int i=0;i<4;i++)
        #pragma unroll
        for (int j=0;j<4;j++) acc[i][j]=0.f;

    const float* xb = x + (size_t)(b*CC + g*CGRP)*PP;

    for (int k=0;k<9;k++){
        {
            int base = ((k*GG + g)*CGRP)*CGRP;
            float* sw = &s_w[0][0];
            for (int e=t; e<4096; e+=256) sw[e] = g_wdt[base + e];
        }
        {
            int y0 = s_iy[k][pix], x0 = s_ix[k][pix];
            float wy = s_fy[k][pix], wx = s_fx[k][pix];
            float w00 = (1.f-wy)*(1.f-wx);
            float w01 = (1.f-wy)*wx;
            float w10 = wy*(1.f-wx);
            float w11 = wy*wx;
            bool vy0 = (y0 >= 0) && (y0 < HH);
            bool vy1 = (y0 >= -1) && (y0 < HH-1);
            bool vx0 = (x0 >= 0) && (x0 < WW);
            bool vx1 = (x0 >= -1) && (x0 < WW-1);
            float m00 = (vy0 && vx0) ? w00 : 0.f;
            float m01 = (vy0 && vx1) ? w01 : 0.f;
            float m10 = (vy1 && vx0) ? w10 : 0.f;
            float m11 = (vy1 && vx1) ? w11 : 0.f;
            int cy0 = min(max(y0,0),HH-1), cy1 = min(max(y0+1,0),HH-1);
            int cx0 = min(max(x0,0),WW-1), cx1 = min(max(x0+1,0),WW-1);
            int i00 = cy0*WW+cx0, i01 = cy0*WW+cx1;
            int i10 = cy1*WW+cx0, i11 = cy1*WW+cx1;
            #pragma unroll 4
            for (int j=0;j<16;j++){
                int cg = cq*16 + j;
                const float* p = xb + (size_t)cg*PP;
                float v = p[i00]*m00 + p[i01]*m01 + p[i10]*m10 + p[i11]*m11;
                s_s[cg][pix] = v;
            }
        }
        __syncthreads();
        #pragma unroll 16
        for (int cg=0; cg<64; cg++){
            float4 sv = *(const float4*)&s_s[cg][pp];
            float4 wv = *(const float4*)&s_w[cg][co_l];
            acc[0][0] += wv.x*sv.x; acc[0][1] += wv.x*sv.y; acc[0][2] += wv.x*sv.z; acc[0][3] += wv.x*sv.w;
            acc[1][0] += wv.y*sv.x; acc[1][1] += wv.y*sv.y; acc[1][2] += wv.y*sv.z; acc[1][3] += wv.y*sv.w;
            acc[2][0] += wv.z*sv.x; acc[2][1] += wv.z*sv.y; acc[2][2] += wv.z*sv.z; acc[2][3] += wv.z*sv.w;
            acc[3][0] += wv.w*sv.x; acc[3][1] += wv.w*sv.y; acc[3][2] += wv.w*sv.z; acc[3][3] += wv.w*sv.w;
        }
        __syncthreads();
    }

    #pragma unroll
    for (int i=0;i<4;i++){
        int co = g*CGRP + co_l + i;
        float4 v = make_float4(acc[i][0], acc[i][1], acc[i][2], acc[i][3]);
        *(float4*)&g_xdir[(size_t)(b*CC + co)*PP + y*WW + pp] = v;
    }
}

// ---------------- g1 conv: 3x3, 256 -> 64, pad=1, bias+bn+silu (ci-chunked) ----------------
__global__ __launch_bounds__(256) void g1_conv2(const float* __restrict__ b_g1,
                                                const float* __restrict__ gamma,
                                                const float* __restrict__ beta,
                                                const float* __restrict__ mean,
                                                const float* __restrict__ var){
    __shared__ float xr[4][3][66];
    __shared__ float ws[4][576];
    int b = blockIdx.x >> 6;
    int y = blockIdx.x & 63;
    int t = threadIdx.x;
    int co_l = (t >> 4) << 2;
    int pp   = (t & 15) << 2;

    float acc[4][4];
    #pragma unroll
    for (int i=0;i<4;i++)
        #pragma unroll
        for (int j=0;j<4;j++) acc[i][j]=0.f;

    for (int c0=0; c0<CC; c0+=4){
        for (int e=t; e<792; e+=256){
            int ci = e/198; int rem = e - ci*198;
            int r = rem/66; int xx = rem - r*66;
            int row = y - 1 + r, col = xx - 1;
            float v = 0.f;
            if (row>=0 && row<HH && col>=0 && col<WW)
                v = g_xdense[((size_t)(b*CC + c0 + ci)*HH + row)*WW + col];
            xr[ci][r][xx] = v;
        }
        for (int e=t; e<2304; e+=256){
            int ci = e/576; int idx = e - ci*576;
            ws[ci][idx] = g_w1t[(c0+ci)*576 + idx];
        }
        __syncthreads();
        #pragma unroll
        for (int ci=0; ci<4; ci++){
            float win[3][6];
            #pragma unroll
            for (int r=0;r<3;r++)
                #pragma unroll
                for (int u=0;u<6;u++) win[r][u] = xr[ci][r][pp+u];
            #pragma unroll
            for (int i=0;i<4;i++){
                #pragma unroll
                for (int kk=0;kk<9;kk++){
                    float wv = ws[ci][(co_l+i)*9 + kk];
                    int r = kk/3, s = kk%3;
                    #pragma unroll
                    for (int j=0;j<4;j++) acc[i][j] += wv * win[r][s+j];
                }
            }
        }
        __syncthreads();
    }

    #pragma unroll
    for (int i=0;i<4;i++){
        int co = co_l + i;
        float bb  = b_g1[co];
        float inv = gamma[co] * rsqrtf(var[co] + 1e-5f);
        float sh  = beta[co] - mean[co]*inv;
        float4 o;
        { float v = (acc[i][0]+bb)*inv + sh; o.x = v*sigm(v); }
        { float v = (acc[i][1]+bb)*inv + sh; o.y = v*sigm(v); }
        { float v = (acc[i][2]+bb)*inv + sh; o.z = v*sigm(v); }
        { float v = (acc[i][3]+bb)*inv + sh; o.w = v*sigm(v); }
        *(float4*)&g_a[(size_t)(b*64 + co)*PP + y*WW + pp] = o;
    }
}

// ---------------- launch ----------------
extern "C" void kernel_launch(void* const* d_in, const int* in_sizes, int n_in,
                              void* d_out, int out_size){
    const float* x       = (const float*)d_in[0];
    const float* x_prev  = (const float*)d_in[1];
    const float* w_off   = (const float*)d_in[2];
    const float* b_off   = (const float*)d_in[3];
    const float* w_def   = (const float*)d_in[4];
    const float* w_cross = (const float*)d_in[5];
    const float* w_g1    = (const float*)d_in[6];
    const float* b_g1    = (const float*)d_in[7];
    const float* g1_gamma= (const float*)d_in[8];
    const float* g1_beta = (const float*)d_in[9];
    const float* g1_mean = (const float*)d_in[10];
    const float* g1_var  = (const float*)d_in[11];
    const float* w_g2    = (const float*)d_in[12];
    const float* b_g2    = (const float*)d_in[13];
    const float* w_out   = (const float*)d_in[14];
    const float* b_out   = (const float*)d_in[15];
    const float* o_gamma = (const float*)d_in[16];
    const float* o_beta  = (const float*)d_in[17];
    const float* o_mean  = (const float*)d_in[18];
    const float* o_var   = (const float*)d_in[19];
    float* out = (float*)d_out;

    cudaFuncSetAttribute(gemm_mma<0>, cudaFuncAttributeMaxDynamicSharedMemorySize, SMEM_GEMM);
    cudaFuncSetAttribute(gemm_mma<1>, cudaFuncAttributeMaxDynamicSharedMemorySize, SMEM_GEMM);
    cudaFuncSetAttribute(gemm_mma<2>, cudaFuncAttributeMaxDynamicSharedMemorySize, SMEM_GEMM);

    transpose_wdef<<<576, 256>>>(w_def);
    transpose_wg1 <<<576, 256>>>(w_g1);
    split_w<0><<<512, 256>>>(w_cross, 256*512);
    split_w<1><<<64,  256>>>(w_g2,   256*64);
    split_w<2><<<256, 256>>>(w_out,  256*256);

    offset_conv2<<<BB*32, 256>>>(x, w_off, b_off);
    deform_conv<<<dim3(HH, GG, BB), 256>>>(x, nullptr);

    trans_split<512,0><<<dim3(PP/32, 16, BB), 256>>>(x_prev);
    gemm_mma<0><<<dim3(PP/128, 2, BB), 256, SMEM_GEMM>>>(nullptr,nullptr,nullptr,nullptr,nullptr,nullptr,nullptr);

    g1_conv2<<<BB*HH, 256>>>(b_g1, g1_gamma, g1_beta, g1_mean, g1_var);

    trans_split<64,1><<<dim3(PP/32, 2, BB), 256>>>(nullptr);
    gemm_mma<1><<<dim3(PP/128, 2, BB), 256, SMEM_GEMM>>>(b_g2,nullptr,nullptr,nullptr,nullptr,nullptr,nullptr);

    trans_split<256,2><<<dim3(PP/32, 8, BB), 256>>>(nullptr);
    gemm_mma<2><<<dim3(PP/128, 2, BB), 256, SMEM_GEMM>>>(b_out, o_gamma, o_beta, o_mean, o_var, x, out);
}

// round 4
// speedup vs baseline: 2.0892x; 1.3261x over previous
#include <cuda_runtime.h>
#include <cuda_bf16.h>
#include <math.h>
#include <stdint.h>

#define BB 4
#define CC 256
#define HH 64
#define WW 64
#define PP (HH*WW)
#define GG 4
#define CGRP 64

// ---------------- device scratch ----------------
__device__ float g_offset[BB*18*PP];
__device__ float g_xdir  [BB*CC*PP];
__device__ float g_xdense[BB*CC*PP];
__device__ float g_a     [BB*64*PP];
__device__ float g_attn  [BB*CC*PP];

// bf16 hi/lo weights for GEMMs
__device__ __nv_bfloat16 g_Achi[256*512], g_Aclo[256*512];
__device__ __nv_bfloat16 g_Ag2hi[256*64], g_Ag2lo[256*64];
__device__ __nv_bfloat16 g_Aohi[256*256], g_Aolo[256*256];
__device__ __nv_bfloat16 g_wdefhi[GG*64*9*64], g_wdeflo[GG*64*9*64];   // [g][co][k][cg]
__device__ __nv_bfloat16 g_w1hi[64*9*256],    g_w1lo[64*9*256];        // [co][k][ci]
// bf16 hi/lo activations [px][ch]
__device__ __nv_bfloat16 g_Bchi[(size_t)BB*PP*512], g_Bclo[(size_t)BB*PP*512];
__device__ __nv_bfloat16 g_Bahi[(size_t)BB*PP*64],  g_Balo[(size_t)BB*PP*64];
__device__ __nv_bfloat16 g_Bohi[(size_t)BB*PP*256], g_Bolo[(size_t)BB*PP*256];
__device__ __nv_bfloat16 g_Bxhi[(size_t)BB*PP*256], g_Bxlo[(size_t)BB*PP*256];

__device__ __forceinline__ float sigm(float v){ return 1.0f/(1.0f+expf(-v)); }

__device__ __forceinline__ uint32_t smem_u32(const void* p){
    uint32_t a;
    asm("{ .reg .u64 tmp; cvta.to.shared.u64 tmp, %1; cvt.u32.u64 %0, tmp; }" : "=r"(a) : "l"(p));
    return a;
}

#define LDSM_X4(r, addr) \
    asm volatile("ldmatrix.sync.aligned.m8n8.x4.shared.b16 {%0,%1,%2,%3}, [%4];" \
        : "=r"((r)[0]), "=r"((r)[1]), "=r"((r)[2]), "=r"((r)[3]) : "r"(addr))
#define LDSM_X2(r, addr) \
    asm volatile("ldmatrix.sync.aligned.m8n8.x2.shared.b16 {%0,%1}, [%2];" \
        : "=r"((r)[0]), "=r"((r)[1]) : "r"(addr))
#define MMA16816(d, a, bfr) \
    asm volatile("mma.sync.aligned.m16n8k16.row.col.f32.bf16.bf16.f32 " \
        "{%0,%1,%2,%3}, {%4,%5,%6,%7}, {%8,%9}, {%0,%1,%2,%3};" \
        : "+f"((d)[0]), "+f"((d)[1]), "+f"((d)[2]), "+f"((d)[3]) \
        : "r"((a)[0]), "r"((a)[1]), "r"((a)[2]), "r"((a)[3]), "r"((bfr)[0]), "r"((bfr)[1]))

__device__ __forceinline__ uint32_t pack_bf(__nv_bfloat16 lo, __nv_bfloat16 hi){
    return (uint32_t)__bfloat16_as_ushort(lo) | ((uint32_t)__bfloat16_as_ushort(hi) << 16);
}

// ---------------- weight hi/lo split ----------------
template<int WSEL>
__global__ void split_w(const float* __restrict__ src, int n){
    int i = blockIdx.x*256 + threadIdx.x;
    if (i >= n) return;
    float v = src[i];
    __nv_bfloat16 h = __float2bfloat16(v);
    __nv_bfloat16 l = __float2bfloat16(v - __bfloat162float(h));
    if (WSEL==0){ g_Achi[i]=h;  g_Aclo[i]=l;  }
    if (WSEL==1){ g_Ag2hi[i]=h; g_Ag2lo[i]=l; }
    if (WSEL==2){ g_Aohi[i]=h;  g_Aolo[i]=l;  }
}

// w_def [256][64][9] -> [g][co][k][cg] hi/lo
__global__ void split_wdef(const float* __restrict__ w_def){
    int id = blockIdx.x*256 + threadIdx.x;
    if (id >= GG*64*9*64) return;
    int cg = id & 63;
    int r  = id >> 6;
    int k  = r % 9;
    int r2 = r / 9;
    int co = r2 & 63;
    int g  = r2 >> 6;
    float v = w_def[ ((g*64 + co)*64 + cg)*9 + k ];
    __nv_bfloat16 h = __float2bfloat16(v);
    g_wdefhi[id] = h;
    g_wdeflo[id] = __float2bfloat16(v - __bfloat162float(h));
}

// w_g1 [64][256][9] -> [co][k][ci] hi/lo
__global__ void split_wg1(const float* __restrict__ w_g1){
    int id = blockIdx.x*256 + threadIdx.x;
    if (id >= 64*9*256) return;
    int ci = id & 255;
    int r  = id >> 8;
    int k  = r % 9;
    int co = r / 9;
    float v = w_g1[(co*256 + ci)*9 + k];
    __nv_bfloat16 h = __float2bfloat16(v);
    g_w1hi[id] = h;
    g_w1lo[id] = __float2bfloat16(v - __bfloat162float(h));
}

// ---------------- transpose+split converters: [ch][px] -> [px][ch] hi/lo ----------------
// SRC 0: concat(g_xdir,x_prev) CH=512 ; SRC 1: g_a CH=64 ; SRC 2: xdense*attn CH=256 ; SRC 3: xdense CH=256
template<int CH, int SRC>
__global__ __launch_bounds__(256) void trans_split(const float* __restrict__ xprev){
    __shared__ float tile[32][33];
    int px0 = blockIdx.x*32;
    int ch0 = blockIdx.y*32;
    int b   = blockIdx.z;
    int t   = threadIdx.x;
    #pragma unroll
    for (int i=0;i<4;i++){
        int e = t + i*256;
        int r = e >> 5, c = e & 31;
        int ch = ch0 + r;
        float v;
        if (SRC==0){
            if (ch < 256) v = g_xdir[((size_t)(b*256+ch))*PP + px0 + c];
            else          v = xprev [((size_t)(b*256+ch-256))*PP + px0 + c];
        } else if (SRC==1){
            v = g_a[((size_t)(b*64+ch))*PP + px0 + c];
        } else if (SRC==2){
            size_t idx = ((size_t)(b*256+ch))*PP + px0 + c;
            v = g_xdense[idx] * g_attn[idx];
        } else {
            v = g_xdense[((size_t)(b*256+ch))*PP + px0 + c];
        }
        tile[r][c] = v;
    }
    __syncthreads();
    #pragma unroll
    for (int i=0;i<4;i++){
        int e = t + i*256;
        int r = e >> 5, c = e & 31;
        float v = tile[c][r];
        __nv_bfloat16 h = __float2bfloat16(v);
        __nv_bfloat16 l = __float2bfloat16(v - __bfloat162float(h));
        size_t o = ((size_t)(b*PP) + px0 + r)*CH + ch0 + c;
        if (SRC==0){ g_Bchi[o]=h; g_Bclo[o]=l; }
        if (SRC==1){ g_Bahi[o]=h; g_Balo[o]=l; }
        if (SRC==2){ g_Bohi[o]=h; g_Bolo[o]=l; }
        if (SRC==3){ g_Bxhi[o]=h; g_Bxlo[o]=l; }
    }
}

// ---------------- mma.sync GEMM: 128co x 128px block, 8 warps (2x4), K-chunks 64 ----------
#define T_STRIDE 72
#define T_BYTES  (128*T_STRIDE*2)       // 18432
#define SMEM_GEMM (4*T_BYTES)           // 73728

__device__ __forceinline__ void fill72(char* dst, const __nv_bfloat16* __restrict__ src,
                                       int ldk, int t){
    #pragma unroll
    for (int i=0;i<4;i++){
        int e = t + i*256;
        int r = e >> 3, c = e & 7;
        uint4 v = *(const uint4*)(src + (size_t)r*ldk + c*8);
        *(uint4*)(dst + r*144 + c*16) = v;
    }
}

template<int MODE>
__global__ __launch_bounds__(256) void gemm_mma(const float* __restrict__ bias,
                                                const float* __restrict__ gamma,
                                                const float* __restrict__ beta,
                                                const float* __restrict__ mean,
                                                const float* __restrict__ var,
                                                const float* __restrict__ resid,
                                                float* __restrict__ outp){
    constexpr int K = (MODE==0) ? 512 : (MODE==1 ? 64 : 256);
    constexpr int CHUNKS = K/64;
    extern __shared__ char smem[];
    uint32_t su = smem_u32(smem);
    int t    = threadIdx.x;
    int lane = t & 31;
    int wid  = t >> 5;
    int wm   = wid >> 2;
    int wn   = wid & 3;
    int px0  = blockIdx.x*128;
    int co0  = blockIdx.y*128;
    int b    = blockIdx.z;

    const __nv_bfloat16* Ahi = (MODE==0) ? g_Achi : (MODE==1 ? g_Ag2hi : g_Aohi);
    const __nv_bfloat16* Alo = (MODE==0) ? g_Aclo : (MODE==1 ? g_Ag2lo : g_Aolo);
    const __nv_bfloat16* Bhi = (MODE==0) ? g_Bchi : (MODE==1 ? g_Bahi : g_Bohi);
    const __nv_bfloat16* Blo = (MODE==0) ? g_Bclo : (MODE==1 ? g_Balo : g_Bolo);

    const __nv_bfloat16* Ab  = Ahi + (size_t)co0*K;
    const __nv_bfloat16* Alb = Alo + (size_t)co0*K;
    const __nv_bfloat16* Bb  = Bhi + ((size_t)(b*PP) + px0)*K;
    const __nv_bfloat16* Blb = Blo + ((size_t)(b*PP) + px0)*K;

    float acc[4][4][4];
    #pragma unroll
    for (int i=0;i<4;i++)
        #pragma unroll
        for (int j=0;j<4;j++)
            #pragma unroll
            for (int q=0;q<4;q++) acc[i][j][q] = 0.f;

    int l16 = lane & 15;
    uint32_t aoff_base = (uint32_t)((wm*64 + (lane & 15))*144 + ((lane >> 4) << 3)*2);
    uint32_t boff_base = (uint32_t)((wn*32 + (l16 & 7))*144 + ((l16 >> 3) << 3)*2);

    for (int c = 0; c < CHUNKS; c++){
        if (c) __syncthreads();
        fill72(smem,             Ab  + c*64, K, t);
        fill72(smem +   T_BYTES, Alb + c*64, K, t);
        fill72(smem + 2*T_BYTES, Bb  + c*64, K, t);
        fill72(smem + 3*T_BYTES, Blb + c*64, K, t);
        __syncthreads();
        #pragma unroll
        for (int ks = 0; ks < 4; ks++){
            uint32_t bh[4][2], bl[4][2];
            #pragma unroll
            for (int na=0;na<4;na++){
                uint32_t boff = boff_base + (uint32_t)(na*8*144 + ks*32);
                LDSM_X2(bh[na], su + 2*T_BYTES + boff);
                LDSM_X2(bl[na], su + 3*T_BYTES + boff);
            }
            #pragma unroll
            for (int ma=0;ma<4;ma++){
                uint32_t aoff = aoff_base + (uint32_t)(ma*16*144 + ks*32);
                uint32_t ah[4], al[4];
                LDSM_X4(ah, su + aoff);
                LDSM_X4(al, su + T_BYTES + aoff);
                #pragma unroll
                for (int na=0;na<4;na++){
                    MMA16816(acc[ma][na], ah, bh[na]);
                    MMA16816(acc[ma][na], al, bh[na]);
                    MMA16816(acc[ma][na], ah, bl[na]);
                }
            }
        }
    }

    #pragma unroll
    for (int ma=0;ma<4;ma++){
        int r0 = co0 + wm*64 + ma*16 + (lane>>2);
        int r1 = r0 + 8;
        float bb0=0.f,bb1=0.f,iv0=0.f,iv1=0.f,sh0=0.f,sh1=0.f;
        if (MODE==1){ bb0 = bias[r0]; bb1 = bias[r1]; }
        if (MODE==2){
            bb0 = bias[r0]; bb1 = bias[r1];
            iv0 = gamma[r0]*rsqrtf(var[r0]+1e-5f); sh0 = beta[r0]-mean[r0]*iv0;
            iv1 = gamma[r1]*rsqrtf(var[r1]+1e-5f); sh1 = beta[r1]-mean[r1]*iv1;
        }
        #pragma unroll
        for (int na=0;na<4;na++){
            int px = px0 + wn*32 + na*8 + ((lane&3)<<1);
            size_t i0 = ((size_t)(b*CC + r0))*PP + px;
            size_t i1 = ((size_t)(b*CC + r1))*PP + px;
            float d0 = acc[ma][na][0], d1 = acc[ma][na][1];
            float d2 = acc[ma][na][2], d3 = acc[ma][na][3];
            if (MODE==0){
                *(float2*)&g_xdense[i0] = make_float2(d0, d1);
                *(float2*)&g_xdense[i1] = make_float2(d2, d3);
            } else if (MODE==1){
                *(float2*)&g_attn[i0] = make_float2(sigm(d0+bb0), sigm(d1+bb0));
                *(float2*)&g_attn[i1] = make_float2(sigm(d2+bb1), sigm(d3+bb1));
            } else {
                float2 rv0 = *(const float2*)&resid[i0];
                float2 rv1 = *(const float2*)&resid[i1];
                float v0 = (d0+bb0)*iv0 + sh0;
                float v1 = (d1+bb0)*iv0 + sh0;
                float v2 = (d2+bb1)*iv1 + sh1;
                float v3 = (d3+bb1)*iv1 + sh1;
                *(float2*)&outp[i0] = make_float2(rv0.x + v0*sigm(v0), rv0.y + v1*sigm(v1));
                *(float2*)&outp[i1] = make_float2(rv1.x + v2*sigm(v2), rv1.y + v3*sigm(v3));
            }
        }
    }
}

// ---------------- deformable conv via mma: block = (px-tile 128, g, b) ----------------
// smem: coords 18432 | Ah 9216 | Al 9216 | Bh 18432 | Bl 18432  = 73728
#define DSM_AH 18432
#define DSM_AL (18432+9216)
#define DSM_BH 36864
#define DSM_BL 55296
#define DSM_TOTAL 73728

__global__ __launch_bounds__(256) void deform_mma(const float* __restrict__ x){
    extern __shared__ char sm[];
    int*   s_y0 = (int*)sm;
    int*   s_x0 = (int*)(sm + 4608);
    float* s_wy = (float*)(sm + 9216);
    float* s_wx = (float*)(sm + 13824);
    uint32_t su = smem_u32(sm);
    int t = threadIdx.x, lane = t & 31, wid = t >> 5;
    int wm = wid >> 2, wn = wid & 3;
    int px0 = blockIdx.x*128;
    int g   = blockIdx.y;
    int b   = blockIdx.z;

    for (int e=t; e<1152; e+=256){
        int k = e >> 7, pxl = e & 127;
        int px = px0 + pxl;
        int y = px >> 6, xc = px & 63;
        float dy = g_offset[(b*18 + 2*k  )*PP + px];
        float dx = g_offset[(b*18 + 2*k+1)*PP + px];
        float py  = (float)y  + (float)(k/3 - 1) + dy;
        float pxx = (float)xc + (float)(k%3 - 1) + dx;
        float fy = floorf(py), fx = floorf(pxx);
        s_y0[e] = (int)fy; s_x0[e] = (int)fx;
        s_wy[e] = py - fy; s_wx[e] = pxx - fx;
    }
    __syncthreads();

    float acc[2][4][4];
    #pragma unroll
    for (int i=0;i<2;i++)
        #pragma unroll
        for (int j=0;j<4;j++)
            #pragma unroll
            for (int q=0;q<4;q++) acc[i][j][q]=0.f;

    const float* xb = x + (size_t)(b*CC + g*64)*PP;
    int l16 = lane & 15;
    uint32_t aoff_base = (uint32_t)((wm*32 + (lane & 15))*144 + ((lane >> 4) << 3)*2);
    uint32_t boff_base = (uint32_t)((wn*32 + (l16 & 7))*144 + ((l16 >> 3) << 3)*2);

    for (int k=0;k<9;k++){
        if (k) __syncthreads();
        // A fill: 64 rows x 64 cols from g_wdef{hi,lo} [g][co][k][cg]
        {
            const __nv_bfloat16* sh = g_wdefhi + (size_t)(g*64*9 + k)*64;
            const __nv_bfloat16* sl = g_wdeflo + (size_t)(g*64*9 + k)*64;
            #pragma unroll
            for (int i=0;i<2;i++){
                int e = t + i*256;
                int r = e >> 3, c = e & 7;
                *(uint4*)(sm + DSM_AH + r*144 + c*16) = *(const uint4*)(sh + (size_t)r*576 + c*8);
                *(uint4*)(sm + DSM_AL + r*144 + c*16) = *(const uint4*)(sl + (size_t)r*576 + c*8);
            }
        }
        // B sample: 128 px x 64 cg (2 threads/px, 32 cg each)
        {
            int pxl = t & 127;
            int cg0 = (t >> 7) << 5;
            int ce = k*128 + pxl;
            int y0 = s_y0[ce], x0 = s_x0[ce];
            float wy = s_wy[ce], wx = s_wx[ce];
            float w00 = (1.f-wy)*(1.f-wx);
            float w01 = (1.f-wy)*wx;
            float w10 = wy*(1.f-wx);
            float w11 = wy*wx;
            bool vy0 = (y0 >= 0) && (y0 < HH);
            bool vy1 = (y0 >= -1) && (y0 < HH-1);
            bool vx0 = (x0 >= 0) && (x0 < WW);
            bool vx1 = (x0 >= -1) && (x0 < WW-1);
            float m00 = (vy0 && vx0) ? w00 : 0.f;
            float m01 = (vy0 && vx1) ? w01 : 0.f;
            float m10 = (vy1 && vx0) ? w10 : 0.f;
            float m11 = (vy1 && vx1) ? w11 : 0.f;
            int cy0 = min(max(y0,0),HH-1), cy1 = min(max(y0+1,0),HH-1);
            int cx0 = min(max(x0,0),WW-1), cx1 = min(max(x0+1,0),WW-1);
            int i00 = cy0*WW+cx0, i01 = cy0*WW+cx1;
            int i10 = cy1*WW+cx0, i11 = cy1*WW+cx1;
            char* bh = sm + DSM_BH + pxl*144 + cg0*2;
            char* bl = sm + DSM_BL + pxl*144 + cg0*2;
            #pragma unroll 4
            for (int j=0;j<32;j+=2){
                const float* p0 = xb + (size_t)(cg0+j)*PP;
                const float* p1 = p0 + PP;
                float v0 = p0[i00]*m00 + p0[i01]*m01 + p0[i10]*m10 + p0[i11]*m11;
                float v1 = p1[i00]*m00 + p1[i01]*m01 + p1[i10]*m10 + p1[i11]*m11;
                __nv_bfloat16 h0 = __float2bfloat16(v0);
                __nv_bfloat16 h1 = __float2bfloat16(v1);
                __nv_bfloat16 l0 = __float2bfloat16(v0 - __bfloat162float(h0));
                __nv_bfloat16 l1 = __float2bfloat16(v1 - __bfloat162float(h1));
                *(uint32_t*)(bh + j*2) = pack_bf(h0, h1);
                *(uint32_t*)(bl + j*2) = pack_bf(l0, l1);
            }
        }
        __syncthreads();
        #pragma unroll
        for (int ks=0;ks<4;ks++){
            uint32_t bh[4][2], bl[4][2];
            #pragma unroll
            for (int na=0;na<4;na++){
                uint32_t boff = boff_base + (uint32_t)(na*8*144 + ks*32);
                LDSM_X2(bh[na], su + DSM_BH + boff);
                LDSM_X2(bl[na], su + DSM_BL + boff);
            }
            #pragma unroll
            for (int ma=0;ma<2;ma++){
                uint32_t aoff = aoff_base + (uint32_t)(ma*16*144 + ks*32);
                uint32_t ah[4], al[4];
                LDSM_X4(ah, su + DSM_AH + aoff);
                LDSM_X4(al, su + DSM_AL + aoff);
                #pragma unroll
                for (int na=0;na<4;na++){
                    MMA16816(acc[ma][na], ah, bh[na]);
                    MMA16816(acc[ma][na], al, bh[na]);
                    MMA16816(acc[ma][na], ah, bl[na]);
                }
            }
        }
    }

    #pragma unroll
    for (int ma=0;ma<2;ma++){
        int r0 = g*64 + wm*32 + ma*16 + (lane>>2);
        int r1 = r0 + 8;
        #pragma unroll
        for (int na=0;na<4;na++){
            int px = px0 + wn*32 + na*8 + ((lane&3)<<1);
            *(float2*)&g_xdir[((size_t)(b*CC + r0))*PP + px] = make_float2(acc[ma][na][0], acc[ma][na][1]);
            *(float2*)&g_xdir[((size_t)(b*CC + r1))*PP + px] = make_float2(acc[ma][na][2], acc[ma][na][3]);
        }
    }
}

// ---------------- g1 3x3 conv as shifted implicit GEMM (256->64, bias+bn+silu) ------------
// smem: Ah 9216 | Al 9216 | Bh 18432 | Bl 18432 = 55296
#define G1_AH 0
#define G1_AL 9216
#define G1_BH 18432
#define G1_BL 36864
#define G1_TOTAL 55296

__global__ __launch_bounds__(256) void g1_mma(const float* __restrict__ bias,
                                              const float* __restrict__ gamma,
                                              const float* __restrict__ beta,
                                              const float* __restrict__ mean,
                                              const float* __restrict__ var){
    extern __shared__ char sm[];
    uint32_t su = smem_u32(sm);
    int t = threadIdx.x, lane = t & 31, wid = t >> 5;
    int wm = wid >> 2, wn = wid & 3;
    int px0 = blockIdx.x*128;
    int b   = blockIdx.y;

    float acc[2][4][4];
    #pragma unroll
    for (int i=0;i<2;i++)
        #pragma unroll
        for (int j=0;j<4;j++)
            #pragma unroll
            for (int q=0;q<4;q++) acc[i][j][q]=0.f;

    int l16 = lane & 15;
    uint32_t aoff_base = (uint32_t)((wm*32 + (lane & 15))*144 + ((lane >> 4) << 3)*2);
    uint32_t boff_base = (uint32_t)((wn*32 + (l16 & 7))*144 + ((l16 >> 3) << 3)*2);

    for (int c = 0; c < 36; c++){
        int k   = c >> 2;
        int sub = c & 3;
        int dy  = k/3 - 1, dx = k%3 - 1;
        int off = dy*WW + dx;
        if (c) __syncthreads();
        // A fill: 64 rows x 64 cols from g_w1{hi,lo} [co][k][ci], row stride 2304
        {
            const __nv_bfloat16* sh = g_w1hi + k*256 + sub*64;
            const __nv_bfloat16* sl = g_w1lo + k*256 + sub*64;
            #pragma unroll
            for (int i=0;i<2;i++){
                int e = t + i*256;
                int r = e >> 3, cc = e & 7;
                *(uint4*)(sm + G1_AH + r*144 + cc*16) = *(const uint4*)(sh + (size_t)r*2304 + cc*8);
                *(uint4*)(sm + G1_AL + r*144 + cc*16) = *(const uint4*)(sl + (size_t)r*2304 + cc*8);
            }
        }
        // B fill: 128 px rows with spatial shift + bounds
        {
            #pragma unroll
            for (int i=0;i<4;i++){
                int e = t + i*256;
                int r = e >> 3, cc = e & 7;
                int px = px0 + r;
                int y = px >> 6, xc = px & 63;
                int yy = y + dy, xx = xc + dx;
                bool valid = ((unsigned)yy < HH) && ((unsigned)xx < WW);
                uint4 vh = make_uint4(0,0,0,0), vl = make_uint4(0,0,0,0);
                if (valid){
                    size_t rb = ((size_t)(b*PP) + px + off)*256 + sub*64;
                    vh = *(const uint4*)(g_Bxhi + rb + cc*8);
                    vl = *(const uint4*)(g_Bxlo + rb + cc*8);
                }
                *(uint4*)(sm + G1_BH + r*144 + cc*16) = vh;
                *(uint4*)(sm + G1_BL + r*144 + cc*16) = vl;
            }
        }
        __syncthreads();
        #pragma unroll
        for (int ks=0;ks<4;ks++){
            uint32_t bh[4][2], bl[4][2];
            #pragma unroll
            for (int na=0;na<4;na++){
                uint32_t boff = boff_base + (uint32_t)(na*8*144 + ks*32);
                LDSM_X2(bh[na], su + G1_BH + boff);
                LDSM_X2(bl[na], su + G1_BL + boff);
            }
            #pragma unroll
            for (int ma=0;ma<2;ma++){
                uint32_t aoff = aoff_base + (uint32_t)(ma*16*144 + ks*32);
                uint32_t ah[4], al[4];
                LDSM_X4(ah, su + G1_AH + aoff);
                LDSM_X4(al, su + G1_AL + aoff);
                #pragma unroll
                for (int na=0;na<4;na++){
                    MMA16816(acc[ma][na], ah, bh[na]);
                    MMA16816(acc[ma][na], al, bh[na]);
                    MMA16816(acc[ma][na], ah, bl[na]);
                }
            }
        }
    }

    #pragma unroll
    for (int ma=0;ma<2;ma++){
        int r0 = wm*32 + ma*16 + (lane>>2);
        int r1 = r0 + 8;
        float bb0 = bias[r0], bb1 = bias[r1];
        float iv0 = gamma[r0]*rsqrtf(var[r0]+1e-5f), sh0 = beta[r0]-mean[r0]*iv0;
        float iv1 = gamma[r1]*rsqrtf(var[r1]+1e-5f), sh1 = beta[r1]-mean[r1]*iv1;
        #pragma unroll
        for (int na=0;na<4;na++){
            int px = px0 + wn*32 + na*8 + ((lane&3)<<1);
            float v0 = (acc[ma][na][0]+bb0)*iv0 + sh0;
            float v1 = (acc[ma][na][1]+bb0)*iv0 + sh0;
            float v2 = (acc[ma][na][2]+bb1)*iv1 + sh1;
            float v3 = (acc[ma][na][3]+bb1)*iv1 + sh1;
            *(float2*)&g_a[((size_t)(b*64 + r0))*PP + px] = make_float2(v0*sigm(v0), v1*sigm(v1));
            *(float2*)&g_a[((size_t)(b*64 + r1))*PP + px] = make_float2(v2*sigm(v2), v3*sigm(v3));
        }
    }
}

// ---------------- offset conv: 3x3, 256->18, pad=1, bias (ci-chunked) ----------------
__global__ __launch_bounds__(256) void offset_conv2(const float* __restrict__ x,
                                                    const float* __restrict__ w_off,
                                                    const float* __restrict__ b_off){
    __shared__ float xr[8][4][66];
    __shared__ float ws[8][18][9];
    int b  = blockIdx.x >> 5;
    int yp = blockIdx.x & 31;
    int y0 = yp*2;
    int t  = threadIdx.x;
    int row  = t >> 7;
    int pix  = t & 63;
    int half = (t >> 6) & 1;
    float acc[9];
    #pragma unroll
    for (int q=0;q<9;q++) acc[q]=0.f;

    for (int c0=0; c0<CC; c0+=8){
        for (int e=t; e<2112; e+=256){
            int ci = e/264; int rem = e - ci*264;
            int rr = rem/66; int xx = rem - rr*66;
            int yy = y0 - 1 + rr, col = xx - 1;
            float v = 0.f;
            if (yy>=0 && yy<HH && col>=0 && col<WW)
                v = x[((b*CC + c0 + ci)*HH + yy)*WW + col];
            xr[ci][rr][xx] = v;
        }
        for (int e=t; e<1296; e+=256){
            int ci = e/162; int rem = e - ci*162;
            int co = rem/9; int k = rem - co*9;
            ws[ci][co][k] = w_off[(co*CC + c0 + ci)*9 + k];
        }
        __syncthreads();
        #pragma unroll
        for (int ci=0; ci<8; ci++){
            float win[3][3];
            #pragma unroll
            for (int r=0;r<3;r++)
                #pragma unroll
                for (int s=0;s<3;s++) win[r][s] = xr[ci][row+r][pix+s];
            #pragma unroll
            for (int q=0;q<9;q++){
                int co = half*9+q;
                float s0 = 0.f;
                #pragma unroll
                for (int r=0;r<3;r++)
                    #pragma unroll
                    for (int s=0;s<3;s++) s0 += ws[ci][co][r*3+s]*win[r][s];
                acc[q] += s0;
            }
        }
        __syncthreads();
    }
    #pragma unroll
    for (int q=0;q<9;q++){
        int co = half*9+q;
        g_offset[((b*18+co)*HH + y0+row)*WW + pix] = acc[q] + b_off[co];
    }
}

// ---------------- launch ----------------
extern "C" void kernel_launch(void* const* d_in, const int* in_sizes, int n_in,
                              void* d_out, int out_size){
    const float* x       = (const float*)d_in[0];
    const float* x_prev  = (const float*)d_in[1];
    const float* w_off   = (const float*)d_in[2];
    const float* b_off   = (const float*)d_in[3];
    const float* w_def   = (const float*)d_in[4];
    const float* w_cross = (const float*)d_in[5];
    const float* w_g1    = (const float*)d_in[6];
    const float* b_g1    = (const float*)d_in[7];
    const float* g1_gamma= (const float*)d_in[8];
    const float* g1_beta = (const float*)d_in[9];
    const float* g1_mean = (const float*)d_in[10];
    const float* g1_var  = (const float*)d_in[11];
    const float* w_g2    = (const float*)d_in[12];
    const float* b_g2    = (const float*)d_in[13];
    const float* w_out   = (const float*)d_in[14];
    const float* b_out   = (const float*)d_in[15];
    const float* o_gamma = (const float*)d_in[16];
    const float* o_beta  = (const float*)d_in[17];
    const float* o_mean  = (const float*)d_in[18];
    const float* o_var   = (const float*)d_in[19];
    float* out = (float*)d_out;

    cudaFuncSetAttribute(gemm_mma<0>, cudaFuncAttributeMaxDynamicSharedMemorySize, SMEM_GEMM);
    cudaFuncSetAttribute(gemm_mma<1>, cudaFuncAttributeMaxDynamicSharedMemorySize, SMEM_GEMM);
    cudaFuncSetAttribute(gemm_mma<2>, cudaFuncAttributeMaxDynamicSharedMemorySize, SMEM_GEMM);
    cudaFuncSetAttribute(deform_mma,  cudaFuncAttributeMaxDynamicSharedMemorySize, DSM_TOTAL);
    cudaFuncSetAttribute(g1_mma,      cudaFuncAttributeMaxDynamicSharedMemorySize, G1_TOTAL);

    split_w<0><<<512, 256>>>(w_cross, 256*512);
    split_w<1><<<64,  256>>>(w_g2,   256*64);
    split_w<2><<<256, 256>>>(w_out,  256*256);
    split_wdef<<<576, 256>>>(w_def);
    split_wg1 <<<576, 256>>>(w_g1);

    offset_conv2<<<BB*32, 256>>>(x, w_off, b_off);
    deform_mma<<<dim3(PP/128, GG, BB), 256, DSM_TOTAL>>>(x);

    trans_split<512,0><<<dim3(PP/32, 16, BB), 256>>>(x_prev);
    gemm_mma<0><<<dim3(PP/128, 2, BB), 256, SMEM_GEMM>>>(nullptr,nullptr,nullptr,nullptr,nullptr,nullptr,nullptr);

    trans_split<256,3><<<dim3(PP/32, 8, BB), 256>>>(nullptr);
    g1_mma<<<dim3(PP/128, BB), 256, G1_TOTAL>>>(b_g1, g1_gamma, g1_beta, g1_mean, g1_var);

    trans_split<64,1><<<dim3(PP/32, 2, BB), 256>>>(nullptr);
    gemm_mma<1><<<dim3(PP/128, 2, BB), 256, SMEM_GEMM>>>(b_g2,nullptr,nullptr,nullptr,nullptr,nullptr,nullptr);

    trans_split<256,2><<<dim3(PP/32, 8, BB), 256>>>(nullptr);
    gemm_mma<2><<<dim3(PP/128, 2, BB), 256, SMEM_GEMM>>>(b_out, o_gamma, o_beta, o_mean, o_var, x, out);
}

// round 5
// speedup vs baseline: 2.8996x; 1.3879x over previous
#include <cuda_runtime.h>
#include <cuda_bf16.h>
#include <math.h>
#include <stdint.h>

#define BB 4
#define CC 256
#define HH 64
#define WW 64
#define PP (HH*WW)
#define GG 4

// ---------------- device scratch ----------------
__device__ float g_offset[BB*18*PP];
__device__ float g_xdense[BB*CC*PP];

// bf16 hi/lo weights
__device__ __nv_bfloat16 g_Achi[256*512], g_Aclo[256*512];         // w_cross
__device__ __nv_bfloat16 g_Ag2hi[256*64], g_Ag2lo[256*64];         // w_g2
__device__ __nv_bfloat16 g_Aohi[256*256], g_Aolo[256*256];         // w_out
__device__ __nv_bfloat16 g_wdefhi[GG*64*9*64], g_wdeflo[GG*64*9*64];   // [g][co][k][cg]
__device__ __nv_bfloat16 g_w1hi[64*9*256],    g_w1lo[64*9*256];        // [co][k][ci]
__device__ __nv_bfloat16 g_woffhi[32*9*256],  g_wofflo[32*9*256];      // [co pad32][k][ci]
// bf16 hi/lo activation B-operands [px][ch]
__device__ __nv_bfloat16 g_Bchi[(size_t)BB*PP*512], g_Bclo[(size_t)BB*PP*512];   // cross in
__device__ __nv_bfloat16 g_Bxhi[(size_t)BB*PP*256], g_Bxlo[(size_t)BB*PP*256];   // xdense
__device__ __nv_bfloat16 g_Bahi[(size_t)BB*PP*64],  g_Balo[(size_t)BB*PP*64];    // g1 out
__device__ __nv_bfloat16 g_Bohi[(size_t)BB*PP*256], g_Bolo[(size_t)BB*PP*256];   // xdense*attn
__device__ __nv_bfloat16 g_Bxinhi[(size_t)BB*PP*256], g_Bxinlo[(size_t)BB*PP*256]; // x

__device__ __forceinline__ float sigm(float v){ return 1.0f/(1.0f+expf(-v)); }

__device__ __forceinline__ void split2(float v, __nv_bfloat16 &h, __nv_bfloat16 &l){
    h = __float2bfloat16(v);
    l = __float2bfloat16(v - __bfloat162float(h));
}

__device__ __forceinline__ uint32_t smem_u32(const void* p){
    uint32_t a;
    asm("{ .reg .u64 tmp; cvta.to.shared.u64 tmp, %1; cvt.u32.u64 %0, tmp; }" : "=r"(a) : "l"(p));
    return a;
}

#define LDSM_X4(r, addr) \
    asm volatile("ldmatrix.sync.aligned.m8n8.x4.shared.b16 {%0,%1,%2,%3}, [%4];" \
        : "=r"((r)[0]), "=r"((r)[1]), "=r"((r)[2]), "=r"((r)[3]) : "r"(addr))
#define LDSM_X2(r, addr) \
    asm volatile("ldmatrix.sync.aligned.m8n8.x2.shared.b16 {%0,%1}, [%2];" \
        : "=r"((r)[0]), "=r"((r)[1]) : "r"(addr))
#define MMA16816(d, a, bfr) \
    asm volatile("mma.sync.aligned.m16n8k16.row.col.f32.bf16.bf16.f32 " \
        "{%0,%1,%2,%3}, {%4,%5,%6,%7}, {%8,%9}, {%0,%1,%2,%3};" \
        : "+f"((d)[0]), "+f"((d)[1]), "+f"((d)[2]), "+f"((d)[3]) \
        : "r"((a)[0]), "r"((a)[1]), "r"((a)[2]), "r"((a)[3]), "r"((bfr)[0]), "r"((bfr)[1]))

// ---------------- merged weight split ----------------
// segments: cross 131072 | g2 16384 | out 65536 | wdef 147456 | wg1 147456 | woff 73728
__global__ void split_all(const float* __restrict__ w_cross,
                          const float* __restrict__ w_g2,
                          const float* __restrict__ w_out,
                          const float* __restrict__ w_def,
                          const float* __restrict__ w_g1,
                          const float* __restrict__ w_off){
    int id = blockIdx.x*256 + threadIdx.x;
    if (id < 131072){
        split2(w_cross[id], g_Achi[id], g_Aclo[id]); return;
    }
    id -= 131072;
    if (id < 16384){
        split2(w_g2[id], g_Ag2hi[id], g_Ag2lo[id]); return;
    }
    id -= 16384;
    if (id < 65536){
        split2(w_out[id], g_Aohi[id], g_Aolo[id]); return;
    }
    id -= 65536;
    if (id < 147456){
        // wdef: [g][co][k][cg] <- w_def[(g*64+co)*64+cg][k]
        int cg = id & 63;
        int r  = id >> 6;
        int k  = r % 9;
        int r2 = r / 9;
        int co = r2 & 63;
        int g  = r2 >> 6;
        split2(w_def[((g*64 + co)*64 + cg)*9 + k], g_wdefhi[id], g_wdeflo[id]);
        return;
    }
    id -= 147456;
    if (id < 147456){
        // wg1: [co][k][ci] <- w_g1[co*256+ci][k]
        int ci = id & 255;
        int r  = id >> 8;
        int k  = r % 9;
        int co = r / 9;
        split2(w_g1[(co*256 + ci)*9 + k], g_w1hi[id], g_w1lo[id]);
        return;
    }
    id -= 147456;
    if (id < 73728){
        // woff: [co pad32][k][ci] <- w_off[co*256+ci][k], zero co>=18
        int ci = id & 255;
        int r  = id >> 8;
        int k  = r % 9;
        int co = r / 9;
        float v = (co < 18) ? w_off[(co*256 + ci)*9 + k] : 0.f;
        split2(v, g_woffhi[id], g_wofflo[id]);
    }
}

// ---------------- converter: [ch][px] fp32 -> [px][ch] hi/lo ----------------
// DST 0: x -> g_Bxin (width 256, base 0) ; DST 1: x_prev -> g_Bc (width 512, base 256)
template<int DST>
__global__ __launch_bounds__(256) void conv_rows(const float* __restrict__ src){
    __shared__ float tile[32][33];
    int px0 = blockIdx.x*32;
    int ch0 = blockIdx.y*32;
    int b   = blockIdx.z;
    int t   = threadIdx.x;
    #pragma unroll
    for (int i=0;i<4;i++){
        int e = t + i*256;
        int r = e >> 5, c = e & 31;
        tile[r][c] = src[((size_t)(b*256+ch0+r))*PP + px0 + c];
    }
    __syncthreads();
    #pragma unroll
    for (int i=0;i<4;i++){
        int e = t + i*256;
        int r = e >> 5, c = e & 31;
        __nv_bfloat16 h, l;
        split2(tile[c][r], h, l);
        if (DST==0){
            size_t o = ((size_t)(b*PP) + px0 + r)*256 + ch0 + c;
            g_Bxinhi[o]=h; g_Bxinlo[o]=l;
        } else {
            size_t o = ((size_t)(b*PP) + px0 + r)*512 + 256 + ch0 + c;
            g_Bchi[o]=h; g_Bclo[o]=l;
        }
    }
}

// ---------------- offset conv as implicit GEMM: 32(18)co x 128px, K=36x64 ----------------
#define OA_H 0
#define OA_L 4608
#define OB_H 9216
#define OB_L 27648
#define OFF_TOTAL 46080

__global__ __launch_bounds__(256) void offset_mma(const float* __restrict__ b_off){
    extern __shared__ char sm[];
    uint32_t su = smem_u32(sm);
    int t = threadIdx.x, lane = t & 31, wid = t >> 5;
    int wn = wid;                 // 8 warps x 16 px
    int px0 = blockIdx.x*128;
    int b   = blockIdx.y;

    float acc[2][2][4];
    #pragma unroll
    for (int i=0;i<2;i++)
        #pragma unroll
        for (int j=0;j<2;j++)
            #pragma unroll
            for (int q=0;q<4;q++) acc[i][j][q]=0.f;

    int l16 = lane & 15;
    uint32_t aoff_base = (uint32_t)((lane & 15)*144 + ((lane >> 4) << 3)*2);
    uint32_t boff_base = (uint32_t)((wn*16 + (l16 & 7))*144 + ((l16 >> 3) << 3)*2);

    for (int c = 0; c < 36; c++){
        int k   = c >> 2;
        int sub = c & 3;
        int dy  = k/3 - 1, dx = k%3 - 1;
        int off = dy*WW + dx;
        if (c) __syncthreads();
        // A: 32 rows x 64 from g_woff [co32][k][ci] row stride 2304
        {
            int r = t >> 3, cc = t & 7;
            const __nv_bfloat16* sh = g_woffhi + (size_t)r*2304 + k*256 + sub*64;
            const __nv_bfloat16* sl = g_wofflo + (size_t)r*2304 + k*256 + sub*64;
            *(uint4*)(sm + OA_H + r*144 + cc*16) = *(const uint4*)(sh + cc*8);
            *(uint4*)(sm + OA_L + r*144 + cc*16) = *(const uint4*)(sl + cc*8);
        }
        // B: 128 px rows with shift
        {
            #pragma unroll
            for (int i=0;i<4;i++){
                int e = t + i*256;
                int r = e >> 3, cc = e & 7;
                int px = px0 + r;
                int y = px >> 6, xc = px & 63;
                int yy = y + dy, xx = xc + dx;
                bool valid = ((unsigned)yy < HH) && ((unsigned)xx < WW);
                uint4 vh = make_uint4(0,0,0,0), vl = make_uint4(0,0,0,0);
                if (valid){
                    size_t rb = ((size_t)(b*PP) + px + off)*256 + sub*64;
                    vh = *(const uint4*)(g_Bxinhi + rb + cc*8);
                    vl = *(const uint4*)(g_Bxinlo + rb + cc*8);
                }
                *(uint4*)(sm + OB_H + r*144 + cc*16) = vh;
                *(uint4*)(sm + OB_L + r*144 + cc*16) = vl;
            }
        }
        __syncthreads();
        #pragma unroll
        for (int ks=0;ks<4;ks++){
            uint32_t bh[2][2], bl[2][2];
            #pragma unroll
            for (int na=0;na<2;na++){
                uint32_t boff = boff_base + (uint32_t)(na*8*144 + ks*32);
                LDSM_X2(bh[na], su + OB_H + boff);
                LDSM_X2(bl[na], su + OB_L + boff);
            }
            #pragma unroll
            for (int ma=0;ma<2;ma++){
                uint32_t aoff = aoff_base + (uint32_t)(ma*16*144 + ks*32);
                uint32_t ah[4], al[4];
                LDSM_X4(ah, su + OA_H + aoff);
                LDSM_X4(al, su + OA_L + aoff);
                #pragma unroll
                for (int na=0;na<2;na++){
                    MMA16816(acc[ma][na], ah, bh[na]);
                    MMA16816(acc[ma][na], al, bh[na]);
                    MMA16816(acc[ma][na], ah, bl[na]);
                }
            }
        }
    }

    #pragma unroll
    for (int ma=0;ma<2;ma++){
        int r0 = ma*16 + (lane>>2);
        int r1 = r0 + 8;
        #pragma unroll
        for (int na=0;na<2;na++){
            int px = px0 + wn*16 + na*8 + ((lane&3)<<1);
            if (r0 < 18){
                float bb = b_off[r0];
                *(float2*)&g_offset[((size_t)(b*18 + r0))*PP + px] =
                    make_float2(acc[ma][na][0]+bb, acc[ma][na][1]+bb);
            }
            if (r1 < 18){
                float bb = b_off[r1];
                *(float2*)&g_offset[((size_t)(b*18 + r1))*PP + px] =
                    make_float2(acc[ma][na][2]+bb, acc[ma][na][3]+bb);
            }
        }
    }
}

// ---------------- deformable conv via mma; epilogue -> g_Bc[px][0:256] slice ----------------
#define DSM_AH 18432
#define DSM_AL (18432+9216)
#define DSM_BH 36864
#define DSM_BL 55296
#define DSM_TOTAL 73728
// transpose staging (reuse): hi at 0, lo at 18432 ([px][64] stride 144B)

__global__ __launch_bounds__(256) void deform_mma(const float* __restrict__ x){
    extern __shared__ char sm[];
    int*   s_y0 = (int*)sm;
    int*   s_x0 = (int*)(sm + 4608);
    float* s_wy = (float*)(sm + 9216);
    float* s_wx = (float*)(sm + 13824);
    uint32_t su = smem_u32(sm);
    int t = threadIdx.x, lane = t & 31, wid = t >> 5;
    int wm = wid >> 2, wn = wid & 3;
    int px0 = blockIdx.x*128;
    int g   = blockIdx.y;
    int b   = blockIdx.z;

    for (int e=t; e<1152; e+=256){
        int k = e >> 7, pxl = e & 127;
        int px = px0 + pxl;
        int y = px >> 6, xc = px & 63;
        float dy = g_offset[(b*18 + 2*k  )*PP + px];
        float dx = g_offset[(b*18 + 2*k+1)*PP + px];
        float py  = (float)y  + (float)(k/3 - 1) + dy;
        float pxx = (float)xc + (float)(k%3 - 1) + dx;
        float fy = floorf(py), fx = floorf(pxx);
        s_y0[e] = (int)fy; s_x0[e] = (int)fx;
        s_wy[e] = py - fy; s_wx[e] = pxx - fx;
    }
    __syncthreads();

    float acc[2][4][4];
    #pragma unroll
    for (int i=0;i<2;i++)
        #pragma unroll
        for (int j=0;j<4;j++)
            #pragma unroll
            for (int q=0;q<4;q++) acc[i][j][q]=0.f;

    const float* xb = x + (size_t)(b*CC + g*64)*PP;
    int l16 = lane & 15;
    uint32_t aoff_base = (uint32_t)((wm*32 + (lane & 15))*144 + ((lane >> 4) << 3)*2);
    uint32_t boff_base = (uint32_t)((wn*32 + (l16 & 7))*144 + ((l16 >> 3) << 3)*2);

    for (int k=0;k<9;k++){
        if (k) __syncthreads();
        {
            const __nv_bfloat16* sh = g_wdefhi + (size_t)(g*64*9 + k)*64;
            const __nv_bfloat16* sl = g_wdeflo + (size_t)(g*64*9 + k)*64;
            #pragma unroll
            for (int i=0;i<2;i++){
                int e = t + i*256;
                int r = e >> 3, c = e & 7;
                *(uint4*)(sm + DSM_AH + r*144 + c*16) = *(const uint4*)(sh + (size_t)r*576 + c*8);
                *(uint4*)(sm + DSM_AL + r*144 + c*16) = *(const uint4*)(sl + (size_t)r*576 + c*8);
            }
        }
        {
            int pxl = t & 127;
            int cg0 = (t >> 7) << 5;
            int ce = k*128 + pxl;
            int y0 = s_y0[ce], x0 = s_x0[ce];
            float wy = s_wy[ce], wx = s_wx[ce];
            float w00 = (1.f-wy)*(1.f-wx);
            float w01 = (1.f-wy)*wx;
            float w10 = wy*(1.f-wx);
            float w11 = wy*wx;
            bool vy0 = (y0 >= 0) && (y0 < HH);
            bool vy1 = (y0 >= -1) && (y0 < HH-1);
            bool vx0 = (x0 >= 0) && (x0 < WW);
            bool vx1 = (x0 >= -1) && (x0 < WW-1);
            float m00 = (vy0 && vx0) ? w00 : 0.f;
            float m01 = (vy0 && vx1) ? w01 : 0.f;
            float m10 = (vy1 && vx0) ? w10 : 0.f;
            float m11 = (vy1 && vx1) ? w11 : 0.f;
            int cy0 = min(max(y0,0),HH-1), cy1 = min(max(y0+1,0),HH-1);
            int cx0 = min(max(x0,0),WW-1), cx1 = min(max(x0+1,0),WW-1);
            int i00 = cy0*WW+cx0, i01 = cy0*WW+cx1;
            int i10 = cy1*WW+cx0, i11 = cy1*WW+cx1;
            char* bh = sm + DSM_BH + pxl*144 + cg0*2;
            char* bl = sm + DSM_BL + pxl*144 + cg0*2;
            #pragma unroll 4
            for (int j=0;j<32;j+=2){
                const float* p0 = xb + (size_t)(cg0+j)*PP;
                const float* p1 = p0 + PP;
                float v0 = p0[i00]*m00 + p0[i01]*m01 + p0[i10]*m10 + p0[i11]*m11;
                float v1 = p1[i00]*m00 + p1[i01]*m01 + p1[i10]*m10 + p1[i11]*m11;
                __nv_bfloat16 h0,l0,h1,l1;
                split2(v0,h0,l0); split2(v1,h1,l1);
                *(uint32_t*)(bh + j*2) = (uint32_t)__bfloat16_as_ushort(h0) | ((uint32_t)__bfloat16_as_ushort(h1)<<16);
                *(uint32_t*)(bl + j*2) = (uint32_t)__bfloat16_as_ushort(l0) | ((uint32_t)__bfloat16_as_ushort(l1)<<16);
            }
        }
        __syncthreads();
        #pragma unroll
        for (int ks=0;ks<4;ks++){
            uint32_t bh[4][2], bl[4][2];
            #pragma unroll
            for (int na=0;na<4;na++){
                uint32_t boff = boff_base + (uint32_t)(na*8*144 + ks*32);
                LDSM_X2(bh[na], su + DSM_BH + boff);
                LDSM_X2(bl[na], su + DSM_BL + boff);
            }
            #pragma unroll
            for (int ma=0;ma<2;ma++){
                uint32_t aoff = aoff_base + (uint32_t)(ma*16*144 + ks*32);
                uint32_t ah[4], al[4];
                LDSM_X4(ah, su + DSM_AH + aoff);
                LDSM_X4(al, su + DSM_AL + aoff);
                #pragma unroll
                for (int na=0;na<4;na++){
                    MMA16816(acc[ma][na], ah, bh[na]);
                    MMA16816(acc[ma][na], al, bh[na]);
                    MMA16816(acc[ma][na], ah, bl[na]);
                }
            }
        }
    }

    // epilogue: transpose to [px][64] hi/lo in smem, write g_Bc slice [g*64, g*64+64)
    __syncthreads();
    #pragma unroll
    for (int ma=0;ma<2;ma++){
        int r0 = wm*32 + ma*16 + (lane>>2);
        int r1 = r0 + 8;
        #pragma unroll
        for (int na=0;na<4;na++){
            int px = wn*32 + na*8 + ((lane&3)<<1);
            __nv_bfloat16 h,l;
            split2(acc[ma][na][0],h,l);
            *(__nv_bfloat16*)(sm + px*144 + r0*2) = h;
            *(__nv_bfloat16*)(sm + 18432 + px*144 + r0*2) = l;
            split2(acc[ma][na][1],h,l);
            *(__nv_bfloat16*)(sm + (px+1)*144 + r0*2) = h;
            *(__nv_bfloat16*)(sm + 18432 + (px+1)*144 + r0*2) = l;
            split2(acc[ma][na][2],h,l);
            *(__nv_bfloat16*)(sm + px*144 + r1*2) = h;
            *(__nv_bfloat16*)(sm + 18432 + px*144 + r1*2) = l;
            split2(acc[ma][na][3],h,l);
            *(__nv_bfloat16*)(sm + (px+1)*144 + r1*2) = h;
            *(__nv_bfloat16*)(sm + 18432 + (px+1)*144 + r1*2) = l;
        }
    }
    __syncthreads();
    #pragma unroll
    for (int i=0;i<4;i++){
        int e = t + i*256;      // 1024 = 128px x 8 chunks
        int r = e >> 3, c8 = e & 7;
        size_t o = ((size_t)(b*PP) + px0 + r)*512 + g*64 + c8*8;
        *(uint4*)(g_Bchi + o) = *(const uint4*)(sm + r*144 + c8*16);
        *(uint4*)(g_Bclo + o) = *(const uint4*)(sm + 18432 + r*144 + c8*16);
    }
}

// ---------------- generic mma GEMM 128co x 128px, fused epilogues ----------------
// MODE 0: cross K=512, B=g_Bc  -> g_xdense fp32 + g_Bx hi/lo slice
// MODE 1: g2    K=64,  B=g_Ba  -> attn*xdense -> g_Bo hi/lo slice
// MODE 2: out   K=256, B=g_Bo  -> bias+bn+silu+resid -> out fp32
#define T_BYTES  (128*144)              // 18432
#define SMEM_GEMM (4*T_BYTES)           // 73728
// transpose staging: [px][128] stride 272B: hi at 0 (34816), lo at 34816

__device__ __forceinline__ void fill72(char* dst, const __nv_bfloat16* __restrict__ src,
                                       int ldk, int t){
    #pragma unroll
    for (int i=0;i<4;i++){
        int e = t + i*256;
        int r = e >> 3, c = e & 7;
        uint4 v = *(const uint4*)(src + (size_t)r*ldk + c*8);
        *(uint4*)(dst + r*144 + c*16) = v;
    }
}

template<int MODE>
__global__ __launch_bounds__(256) void gemm_mma(const float* __restrict__ bias,
                                                const float* __restrict__ gamma,
                                                const float* __restrict__ beta,
                                                const float* __restrict__ mean,
                                                const float* __restrict__ var,
                                                const float* __restrict__ resid,
                                                float* __restrict__ outp){
    constexpr int K = (MODE==0) ? 512 : (MODE==1 ? 64 : 256);
    constexpr int CHUNKS = K/64;
    extern __shared__ char smem[];
    uint32_t su = smem_u32(smem);
    int t    = threadIdx.x;
    int lane = t & 31;
    int wid  = t >> 5;
    int wm   = wid >> 2;
    int wn   = wid & 3;
    int px0  = blockIdx.x*128;
    int co0  = blockIdx.y*128;
    int b    = blockIdx.z;

    const __nv_bfloat16* Ahi = (MODE==0) ? g_Achi : (MODE==1 ? g_Ag2hi : g_Aohi);
    const __nv_bfloat16* Alo = (MODE==0) ? g_Aclo : (MODE==1 ? g_Ag2lo : g_Aolo);
    const __nv_bfloat16* Bhi = (MODE==0) ? g_Bchi : (MODE==1 ? g_Bahi : g_Bohi);
    const __nv_bfloat16* Blo = (MODE==0) ? g_Bclo : (MODE==1 ? g_Balo : g_Bolo);

    const __nv_bfloat16* Ab  = Ahi + (size_t)co0*K;
    const __nv_bfloat16* Alb = Alo + (size_t)co0*K;
    const __nv_bfloat16* Bb  = Bhi + ((size_t)(b*PP) + px0)*K;
    const __nv_bfloat16* Blb = Blo + ((size_t)(b*PP) + px0)*K;

    float acc[4][4][4];
    #pragma unroll
    for (int i=0;i<4;i++)
        #pragma unroll
        for (int j=0;j<4;j++)
            #pragma unroll
            for (int q=0;q<4;q++) acc[i][j][q] = 0.f;

    int l16 = lane & 15;
    uint32_t aoff_base = (uint32_t)((wm*64 + (lane & 15))*144 + ((lane >> 4) << 3)*2);
    uint32_t boff_base = (uint32_t)((wn*32 + (l16 & 7))*144 + ((l16 >> 3) << 3)*2);

    for (int c = 0; c < CHUNKS; c++){
        if (c) __syncthreads();
        fill72(smem,             Ab  + c*64, K, t);
        fill72(smem +   T_BYTES, Alb + c*64, K, t);
        fill72(smem + 2*T_BYTES, Bb  + c*64, K, t);
        fill72(smem + 3*T_BYTES, Blb + c*64, K, t);
        __syncthreads();
        #pragma unroll
        for (int ks = 0; ks < 4; ks++){
            uint32_t bh[4][2], bl[4][2];
            #pragma unroll
            for (int na=0;na<4;na++){
                uint32_t boff = boff_base + (uint32_t)(na*8*144 + ks*32);
                LDSM_X2(bh[na], su + 2*T_BYTES + boff);
                LDSM_X2(bl[na], su + 3*T_BYTES + boff);
            }
            #pragma unroll
            for (int ma=0;ma<4;ma++){
                uint32_t aoff = aoff_base + (uint32_t)(ma*16*144 + ks*32);
                uint32_t ah[4], al[4];
                LDSM_X4(ah, su + aoff);
                LDSM_X4(al, su + T_BYTES + aoff);
                #pragma unroll
                for (int na=0;na<4;na++){
                    MMA16816(acc[ma][na], ah, bh[na]);
                    MMA16816(acc[ma][na], al, bh[na]);
                    MMA16816(acc[ma][na], ah, bl[na]);
                }
            }
        }
    }

    if (MODE == 2){
        // direct epilogue: bias + bn + silu + residual -> out
        #pragma unroll
        for (int ma=0;ma<4;ma++){
            int r0 = co0 + wm*64 + ma*16 + (lane>>2);
            int r1 = r0 + 8;
            float bb0 = bias[r0], bb1 = bias[r1];
            float iv0 = gamma[r0]*rsqrtf(var[r0]+1e-5f), sh0 = beta[r0]-mean[r0]*iv0;
            float iv1 = gamma[r1]*rsqrtf(var[r1]+1e-5f), sh1 = beta[r1]-mean[r1]*iv1;
            #pragma unroll
            for (int na=0;na<4;na++){
                int px = px0 + wn*32 + na*8 + ((lane&3)<<1);
                size_t i0 = ((size_t)(b*CC + r0))*PP + px;
                size_t i1 = ((size_t)(b*CC + r1))*PP + px;
                float2 rv0 = *(const float2*)&resid[i0];
                float2 rv1 = *(const float2*)&resid[i1];
                float v0 = (acc[ma][na][0]+bb0)*iv0 + sh0;
                float v1 = (acc[ma][na][1]+bb0)*iv0 + sh0;
                float v2 = (acc[ma][na][2]+bb1)*iv1 + sh1;
                float v3 = (acc[ma][na][3]+bb1)*iv1 + sh1;
                *(float2*)&outp[i0] = make_float2(rv0.x + v0*sigm(v0), rv0.y + v1*sigm(v1));
                *(float2*)&outp[i1] = make_float2(rv1.x + v2*sigm(v2), rv1.y + v3*sigm(v3));
            }
        }
        return;
    }

    // MODE 0/1: stage transposed bf16 hi/lo and stream out
    __syncthreads();
    #pragma unroll
    for (int ma=0;ma<4;ma++){
        int r0 = wm*64 + ma*16 + (lane>>2);     // local co
        int r1 = r0 + 8;
        int gr0 = co0 + r0, gr1 = co0 + r1;
        float bb0=0.f, bb1=0.f;
        if (MODE==1){ bb0 = bias[gr0]; bb1 = bias[gr1]; }
        #pragma unroll
        for (int na=0;na<4;na++){
            int px = wn*32 + na*8 + ((lane&3)<<1);
            float d0 = acc[ma][na][0], d1 = acc[ma][na][1];
            float d2 = acc[ma][na][2], d3 = acc[ma][na][3];
            float v0, v1, v2, v3;
            if (MODE==0){
                size_t i0 = ((size_t)(b*CC + gr0))*PP + px0 + px;
                size_t i1 = ((size_t)(b*CC + gr1))*PP + px0 + px;
                *(float2*)&g_xdense[i0] = make_float2(d0, d1);
                *(float2*)&g_xdense[i1] = make_float2(d2, d3);
                v0 = d0; v1 = d1; v2 = d2; v3 = d3;
            } else {
                size_t i0 = ((size_t)(b*CC + gr0))*PP + px0 + px;
                size_t i1 = ((size_t)(b*CC + gr1))*PP + px0 + px;
                float2 x0 = *(const float2*)&g_xdense[i0];
                float2 x1 = *(const float2*)&g_xdense[i1];
                v0 = x0.x * sigm(d0+bb0);
                v1 = x0.y * sigm(d1+bb0);
                v2 = x1.x * sigm(d2+bb1);
                v3 = x1.y * sigm(d3+bb1);
            }
            __nv_bfloat16 h,l;
            split2(v0,h,l);
            *(__nv_bfloat16*)(smem + px*272 + r0*2) = h;
            *(__nv_bfloat16*)(smem + 34816 + px*272 + r0*2) = l;
            split2(v1,h,l);
            *(__nv_bfloat16*)(smem + (px+1)*272 + r0*2) = h;
            *(__nv_bfloat16*)(smem + 34816 + (px+1)*272 + r0*2) = l;
            split2(v2,h,l);
            *(__nv_bfloat16*)(smem + px*272 + r1*2) = h;
            *(__nv_bfloat16*)(smem + 34816 + px*272 + r1*2) = l;
            split2(v3,h,l);
            *(__nv_bfloat16*)(smem + (px+1)*272 + r1*2) = h;
            *(__nv_bfloat16*)(smem + 34816 + (px+1)*272 + r1*2) = l;
        }
    }
    __syncthreads();
    {
        __nv_bfloat16* Dh = (MODE==0) ? g_Bxhi : g_Bohi;
        __nv_bfloat16* Dl = (MODE==0) ? g_Bxlo : g_Bolo;
        #pragma unroll
        for (int i=0;i<8;i++){
            int e = t + i*256;      // 2048 = 128px x 16 chunks
            int r = e >> 4, c16 = e & 15;
            size_t o = ((size_t)(b*PP) + px0 + r)*256 + co0 + c16*8;
            *(uint4*)(Dh + o) = *(const uint4*)(smem + r*272 + c16*16);
            *(uint4*)(Dl + o) = *(const uint4*)(smem + 34816 + r*272 + c16*16);
        }
    }
}

// ---------------- g1 3x3 conv implicit GEMM -> g_Ba [px][64] hi/lo ----------------
#define G1_AH 0
#define G1_AL 9216
#define G1_BH 18432
#define G1_BL 36864
#define G1_TOTAL 55296

__global__ __launch_bounds__(256) void g1_mma(const float* __restrict__ bias,
                                              const float* __restrict__ gamma,
                                              const float* __restrict__ beta,
                                              const float* __restrict__ mean,
                                              const float* __restrict__ var){
    extern __shared__ char sm[];
    uint32_t su = smem_u32(sm);
    int t = threadIdx.x, lane = t & 31, wid = t >> 5;
    int wm = wid >> 2, wn = wid & 3;
    int px0 = blockIdx.x*128;
    int b   = blockIdx.y;

    float acc[2][4][4];
    #pragma unroll
    for (int i=0;i<2;i++)
        #pragma unroll
        for (int j=0;j<4;j++)
            #pragma unroll
            for (int q=0;q<4;q++) acc[i][j][q]=0.f;

    int l16 = lane & 15;
    uint32_t aoff_base = (uint32_t)((wm*32 + (lane & 15))*144 + ((lane >> 4) << 3)*2);
    uint32_t boff_base = (uint32_t)((wn*32 + (l16 & 7))*144 + ((l16 >> 3) << 3)*2);

    for (int c = 0; c < 36; c++){
        int k   = c >> 2;
        int sub = c & 3;
        int dy  = k/3 - 1, dx = k%3 - 1;
        int off = dy*WW + dx;
        if (c) __syncthreads();
        {
            const __nv_bfloat16* sh = g_w1hi + k*256 + sub*64;
            const __nv_bfloat16* sl = g_w1lo + k*256 + sub*64;
            #pragma unroll
            for (int i=0;i<2;i++){
                int e = t + i*256;
                int r = e >> 3, cc = e & 7;
                *(uint4*)(sm + G1_AH + r*144 + cc*16) = *(const uint4*)(sh + (size_t)r*2304 + cc*8);
                *(uint4*)(sm + G1_AL + r*144 + cc*16) = *(const uint4*)(sl + (size_t)r*2304 + cc*8);
            }
        }
        {
            #pragma unroll
            for (int i=0;i<4;i++){
                int e = t + i*256;
                int r = e >> 3, cc = e & 7;
                int px = px0 + r;
                int y = px >> 6, xc = px & 63;
                int yy = y + dy, xx = xc + dx;
                bool valid = ((unsigned)yy < HH) && ((unsigned)xx < WW);
                uint4 vh = make_uint4(0,0,0,0), vl = make_uint4(0,0,0,0);
                if (valid){
                    size_t rb = ((size_t)(b*PP) + px + off)*256 + sub*64;
                    vh = *(const uint4*)(g_Bxhi + rb + cc*8);
                    vl = *(const uint4*)(g_Bxlo + rb + cc*8);
                }
                *(uint4*)(sm + G1_BH + r*144 + cc*16) = vh;
                *(uint4*)(sm + G1_BL + r*144 + cc*16) = vl;
            }
        }
        __syncthreads();
        #pragma unroll
        for (int ks=0;ks<4;ks++){
            uint32_t bh[4][2], bl[4][2];
            #pragma unroll
            for (int na=0;na<4;na++){
                uint32_t boff = boff_base + (uint32_t)(na*8*144 + ks*32);
                LDSM_X2(bh[na], su + G1_BH + boff);
                LDSM_X2(bl[na], su + G1_BL + boff);
            }
            #pragma unroll
            for (int ma=0;ma<2;ma++){
                uint32_t aoff = aoff_base + (uint32_t)(ma*16*144 + ks*32);
                uint32_t ah[4], al[4];
                LDSM_X4(ah, su + G1_AH + aoff);
                LDSM_X4(al, su + G1_AL + aoff);
                #pragma unroll
                for (int na=0;na<4;na++){
                    MMA16816(acc[ma][na], ah, bh[na]);
                    MMA16816(acc[ma][na], al, bh[na]);
                    MMA16816(acc[ma][na], ah, bl[na]);
                }
            }
        }
    }

    // epilogue: bn+silu, transpose -> g_Ba [px][64] hi/lo
    __syncthreads();
    #pragma unroll
    for (int ma=0;ma<2;ma++){
        int r0 = wm*32 + ma*16 + (lane>>2);
        int r1 = r0 + 8;
        float bb0 = bias[r0], bb1 = bias[r1];
        float iv0 = gamma[r0]*rsqrtf(var[r0]+1e-5f), sh0 = beta[r0]-mean[r0]*iv0;
        float iv1 = gamma[r1]*rsqrtf(var[r1]+1e-5f), sh1 = beta[r1]-mean[r1]*iv1;
        #pragma unroll
        for (int na=0;na<4;na++){
            int px = wn*32 + na*8 + ((lane&3)<<1);
            float v0 = (acc[ma][na][0]+bb0)*iv0 + sh0; v0 = v0*sigm(v0);
            float v1 = (acc[ma][na][1]+bb0)*iv0 + sh0; v1 = v1*sigm(v1);
            float v2 = (acc[ma][na][2]+bb1)*iv1 + sh1; v2 = v2*sigm(v2);
            float v3 = (acc[ma][na][3]+bb1)*iv1 + sh1; v3 = v3*sigm(v3);
            __nv_bfloat16 h,l;
            split2(v0,h,l);
            *(__nv_bfloat16*)(sm + px*144 + r0*2) = h;
            *(__nv_bfloat16*)(sm + 18432 + px*144 + r0*2) = l;
            split2(v1,h,l);
            *(__nv_bfloat16*)(sm + (px+1)*144 + r0*2) = h;
            *(__nv_bfloat16*)(sm + 18432 + (px+1)*144 + r0*2) = l;
            split2(v2,h,l);
            *(__nv_bfloat16*)(sm + px*144 + r1*2) = h;
            *(__nv_bfloat16*)(sm + 18432 + px*144 + r1*2) = l;
            split2(v3,h,l);
            *(__nv_bfloat16*)(sm + (px+1)*144 + r1*2) = h;
            *(__nv_bfloat16*)(sm + 18432 + (px+1)*144 + r1*2) = l;
        }
    }
    __syncthreads();
    #pragma unroll
    for (int i=0;i<4;i++){
        int e = t + i*256;      // 1024 = 128px x 8 chunks
        int r = e >> 3, c8 = e & 7;
        size_t o = ((size_t)(b*PP) + px0 + r)*64 + c8*8;
        *(uint4*)(g_Bahi + o) = *(const uint4*)(sm + r*144 + c8*16);
        *(uint4*)(g_Balo + o) = *(const uint4*)(sm + 18432 + r*144 + c8*16);
    }
}

// ---------------- launch ----------------
extern "C" void kernel_launch(void* const* d_in, const int* in_sizes, int n_in,
                              void* d_out, int out_size){
    const float* x       = (const float*)d_in[0];
    const float* x_prev  = (const float*)d_in[1];
    const float* w_off   = (const float*)d_in[2];
    const float* b_off   = (const float*)d_in[3];
    const float* w_def   = (const float*)d_in[4];
    const float* w_cross = (const float*)d_in[5];
    const float* w_g1    = (const float*)d_in[6];
    const float* b_g1    = (const float*)d_in[7];
    const float* g1_gamma= (const float*)d_in[8];
    const float* g1_beta = (const float*)d_in[9];
    const float* g1_mean = (const float*)d_in[10];
    const float* g1_var  = (const float*)d_in[11];
    const float* w_g2    = (const float*)d_in[12];
    const float* b_g2    = (const float*)d_in[13];
    const float* w_out   = (const float*)d_in[14];
    const float* b_out   = (const float*)d_in[15];
    const float* o_gamma = (const float*)d_in[16];
    const float* o_beta  = (const float*)d_in[17];
    const float* o_mean  = (const float*)d_in[18];
    const float* o_var   = (const float*)d_in[19];
    float* out = (float*)d_out;

    cudaFuncSetAttribute(gemm_mma<0>, cudaFuncAttributeMaxDynamicSharedMemorySize, SMEM_GEMM);
    cudaFuncSetAttribute(gemm_mma<1>, cudaFuncAttributeMaxDynamicSharedMemorySize, SMEM_GEMM);
    cudaFuncSetAttribute(gemm_mma<2>, cudaFuncAttributeMaxDynamicSharedMemorySize, SMEM_GEMM);
    cudaFuncSetAttribute(deform_mma,  cudaFuncAttributeMaxDynamicSharedMemorySize, DSM_TOTAL);
    cudaFuncSetAttribute(g1_mma,      cudaFuncAttributeMaxDynamicSharedMemorySize, G1_TOTAL);
    cudaFuncSetAttribute(offset_mma,  cudaFuncAttributeMaxDynamicSharedMemorySize, OFF_TOTAL);

    split_all<<<2272, 256>>>(w_cross, w_g2, w_out, w_def, w_g1, w_off);
    conv_rows<0><<<dim3(PP/32, 8, BB), 256>>>(x);
    conv_rows<1><<<dim3(PP/32, 8, BB), 256>>>(x_prev);

    offset_mma<<<dim3(PP/128, BB), 256, OFF_TOTAL>>>(b_off);
    deform_mma<<<dim3(PP/128, GG, BB), 256, DSM_TOTAL>>>(x);

    gemm_mma<0><<<dim3(PP/128, 2, BB), 256, SMEM_GEMM>>>(nullptr,nullptr,nullptr,nullptr,nullptr,nullptr,nullptr);
    g1_mma<<<dim3(PP/128, BB), 256, G1_TOTAL>>>(b_g1, g1_gamma, g1_beta, g1_mean, g1_var);
    gemm_mma<1><<<dim3(PP/128, 2, BB), 256, SMEM_GEMM>>>(b_g2,nullptr,nullptr,nullptr,nullptr,nullptr,nullptr);
    gemm_mma<2><<<dim3(PP/128, 2, BB), 256, SMEM_GEMM>>>(b_out, o_gamma, o_beta, o_mean, o_var, x, out);
}

// round 6
// speedup vs baseline: 3.0360x; 1.0470x over previous
#include <cuda_runtime.h>
#include <cuda_bf16.h>
#include <math.h>
#include <stdint.h>

#define BB 4
#define CC 256
#define HH 64
#define WW 64
#define PP (HH*WW)
#define GG 4

// ---------------- device scratch ----------------
__device__ float g_offset[BB*18*PP];
__device__ float g_xdense[BB*CC*PP];

// bf16 hi/lo weights
__device__ __nv_bfloat16 g_Achi[256*512], g_Aclo[256*512];         // w_cross
__device__ __nv_bfloat16 g_Ag2hi[256*64], g_Ag2lo[256*64];         // w_g2
__device__ __nv_bfloat16 g_Aohi[256*256], g_Aolo[256*256];         // w_out
__device__ __nv_bfloat16 g_wdefhi[GG*64*9*64], g_wdeflo[GG*64*9*64];   // [g][co][k][cg]
__device__ __nv_bfloat16 g_w1hi[64*9*256],    g_w1lo[64*9*256];        // [co][k][ci]
__device__ __nv_bfloat16 g_woffhi[32*9*256],  g_wofflo[32*9*256];      // [co pad32][k][ci]
// bf16 hi/lo activation B-operands [px][ch]
__device__ __nv_bfloat16 g_Bchi[(size_t)BB*PP*512], g_Bclo[(size_t)BB*PP*512];   // cross in
__device__ __nv_bfloat16 g_Bxhi[(size_t)BB*PP*256], g_Bxlo[(size_t)BB*PP*256];   // xdense
__device__ __nv_bfloat16 g_Bahi[(size_t)BB*PP*64],  g_Balo[(size_t)BB*PP*64];    // g1 out
__device__ __nv_bfloat16 g_Bohi[(size_t)BB*PP*256], g_Bolo[(size_t)BB*PP*256];   // xdense*attn
__device__ __nv_bfloat16 g_Bxinhi[(size_t)BB*PP*256], g_Bxinlo[(size_t)BB*PP*256]; // x

__device__ __forceinline__ float sigm(float v){ return 1.0f/(1.0f+expf(-v)); }

__device__ __forceinline__ void split2(float v, __nv_bfloat16 &h, __nv_bfloat16 &l){
    h = __float2bfloat16(v);
    l = __float2bfloat16(v - __bfloat162float(h));
}

__device__ __forceinline__ uint32_t smem_u32(const void* p){
    uint32_t a;
    asm("{ .reg .u64 tmp; cvta.to.shared.u64 tmp, %1; cvt.u32.u64 %0, tmp; }" : "=r"(a) : "l"(p));
    return a;
}

#define LDSM_X4(r, addr) \
    asm volatile("ldmatrix.sync.aligned.m8n8.x4.shared.b16 {%0,%1,%2,%3}, [%4];" \
        : "=r"((r)[0]), "=r"((r)[1]), "=r"((r)[2]), "=r"((r)[3]) : "r"(addr))
#define LDSM_X2(r, addr) \
    asm volatile("ldmatrix.sync.aligned.m8n8.x2.shared.b16 {%0,%1}, [%2];" \
        : "=r"((r)[0]), "=r"((r)[1]) : "r"(addr))
#define MMA16816(d, a, bfr) \
    asm volatile("mma.sync.aligned.m16n8k16.row.col.f32.bf16.bf16.f32 " \
        "{%0,%1,%2,%3}, {%4,%5,%6,%7}, {%8,%9}, {%0,%1,%2,%3};" \
        : "+f"((d)[0]), "+f"((d)[1]), "+f"((d)[2]), "+f"((d)[3]) \
        : "r"((a)[0]), "r"((a)[1]), "r"((a)[2]), "r"((a)[3]), "r"((bfr)[0]), "r"((bfr)[1]))

#define CP16(dst, src) \
    asm volatile("cp.async.cg.shared.global [%0], [%1], 16;" :: "r"(dst), "l"(src))
#define CP_COMMIT() asm volatile("cp.async.commit_group;" ::: "memory")
#define CP_WAIT0()  asm volatile("cp.async.wait_group 0;" ::: "memory")

// ---------------- merged weight split ----------------
__global__ void split_all(const float* __restrict__ w_cross,
                          const float* __restrict__ w_g2,
                          const float* __restrict__ w_out,
                          const float* __restrict__ w_def,
                          const float* __restrict__ w_g1,
                          const float* __restrict__ w_off){
    int id = blockIdx.x*256 + threadIdx.x;
    if (id < 131072){
        split2(w_cross[id], g_Achi[id], g_Aclo[id]); return;
    }
    id -= 131072;
    if (id < 16384){
        split2(w_g2[id], g_Ag2hi[id], g_Ag2lo[id]); return;
    }
    id -= 16384;
    if (id < 65536){
        split2(w_out[id], g_Aohi[id], g_Aolo[id]); return;
    }
    id -= 65536;
    if (id < 147456){
        int cg = id & 63;
        int r  = id >> 6;
        int k  = r % 9;
        int r2 = r / 9;
        int co = r2 & 63;
        int g  = r2 >> 6;
        split2(w_def[((g*64 + co)*64 + cg)*9 + k], g_wdefhi[id], g_wdeflo[id]);
        return;
    }
    id -= 147456;
    if (id < 147456){
        int ci = id & 255;
        int r  = id >> 8;
        int k  = r % 9;
        int co = r / 9;
        split2(w_g1[(co*256 + ci)*9 + k], g_w1hi[id], g_w1lo[id]);
        return;
    }
    id -= 147456;
    if (id < 73728){
        int ci = id & 255;
        int r  = id >> 8;
        int k  = r % 9;
        int co = r / 9;
        float v = (co < 18) ? w_off[(co*256 + ci)*9 + k] : 0.f;
        split2(v, g_woffhi[id], g_wofflo[id]);
    }
}

// ---------------- converter: [ch][px] fp32 -> [px][ch] hi/lo ----------------
template<int DST>
__global__ __launch_bounds__(256) void conv_rows(const float* __restrict__ src){
    __shared__ float tile[32][33];
    int px0 = blockIdx.x*32;
    int ch0 = blockIdx.y*32;
    int b   = blockIdx.z;
    int t   = threadIdx.x;
    #pragma unroll
    for (int i=0;i<4;i++){
        int e = t + i*256;
        int r = e >> 5, c = e & 31;
        tile[r][c] = src[((size_t)(b*256+ch0+r))*PP + px0 + c];
    }
    __syncthreads();
    #pragma unroll
    for (int i=0;i<4;i++){
        int e = t + i*256;
        int r = e >> 5, c = e & 31;
        __nv_bfloat16 h, l;
        split2(tile[c][r], h, l);
        if (DST==0){
            size_t o = ((size_t)(b*PP) + px0 + r)*256 + ch0 + c;
            g_Bxinhi[o]=h; g_Bxinlo[o]=l;
        } else {
            size_t o = ((size_t)(b*PP) + px0 + r)*512 + 256 + ch0 + c;
            g_Bchi[o]=h; g_Bclo[o]=l;
        }
    }
}

// ---------------- offset conv implicit GEMM (cp.async 2-stage): 32co x 64px ----------------
// stage layout: AH 0 (4608) | AL 4608 | BH 9216 (9216) | BL 18432 ; stage=27648
#define OFF_STAGE 27648
#define OFF_TOTAL (2*OFF_STAGE)

__device__ __forceinline__ void off_copy(uint32_t su, char* smc, int s, int c, int t, int b, int px0){
    int k = c >> 2, sub = c & 3;
    int dy = k/3 - 1, dx = k%3 - 1;
    int off = dy*WW + dx;
    uint32_t base = su + s*OFF_STAGE;
    {
        int r = t >> 3, c8 = t & 7;
        uint32_t so = (uint32_t)(r*144 + c8*16);
        const __nv_bfloat16* ph = g_woffhi + (size_t)r*2304 + k*256 + sub*64 + c8*8;
        const __nv_bfloat16* pl = g_wofflo + (size_t)r*2304 + k*256 + sub*64 + c8*8;
        CP16(base + so, ph);
        CP16(base + 4608 + so, pl);
    }
    #pragma unroll
    for (int i=0;i<2;i++){
        int e = t + i*256;
        int r = e >> 3, c8 = e & 7;
        uint32_t so = (uint32_t)(r*144 + c8*16);
        int px = px0 + r;
        int y = px >> 6, xc = px & 63;
        int yy = y + dy, xx = xc + dx;
        bool valid = ((unsigned)yy < HH) && ((unsigned)xx < WW);
        if (valid){
            size_t rb = ((size_t)(b*PP) + px + off)*256 + sub*64 + c8*8;
            CP16(base + 9216 + so,  g_Bxinhi + rb);
            CP16(base + 18432 + so, g_Bxinlo + rb);
        } else {
            *(uint4*)(smc + s*OFF_STAGE + 9216 + so)  = make_uint4(0,0,0,0);
            *(uint4*)(smc + s*OFF_STAGE + 18432 + so) = make_uint4(0,0,0,0);
        }
    }
}

__global__ __launch_bounds__(256) void offset_mma(const float* __restrict__ b_off){
    extern __shared__ char sm[];
    uint32_t su = smem_u32(sm);
    int t = threadIdx.x, lane = t & 31, wid = t >> 5;
    int wn = wid;                 // 8 warps x 8 px
    int px0 = blockIdx.x*64;
    int b   = blockIdx.y;

    float acc[2][4];
    #pragma unroll
    for (int i=0;i<2;i++)
        #pragma unroll
        for (int q=0;q<4;q++) acc[i][q]=0.f;

    int l16 = lane & 15;
    uint32_t aoff_base = (uint32_t)((lane & 15)*144 + ((lane >> 4) << 3)*2);
    uint32_t boff_base = (uint32_t)((wn*8 + (l16 & 7))*144 + ((l16 >> 3) << 3)*2);

    off_copy(su, sm, 0, 0, t, b, px0);
    CP_COMMIT();

    for (int c = 0; c < 36; c++){
        CP_WAIT0();
        __syncthreads();
        if (c+1 < 36){ off_copy(su, sm, (c+1)&1, c+1, t, b, px0); CP_COMMIT(); }
        uint32_t sb = su + (c&1)*OFF_STAGE;
        #pragma unroll
        for (int ks=0;ks<4;ks++){
            uint32_t bh[2], bl[2];
            LDSM_X2(bh, sb + 9216  + boff_base + ks*32);
            LDSM_X2(bl, sb + 18432 + boff_base + ks*32);
            #pragma unroll
            for (int ma=0;ma<2;ma++){
                uint32_t aoff = aoff_base + (uint32_t)(ma*16*144 + ks*32);
                uint32_t ah[4], al[4];
                LDSM_X4(ah, sb + aoff);
                LDSM_X4(al, sb + 4608 + aoff);
                MMA16816(acc[ma], ah, bh);
                MMA16816(acc[ma], al, bh);
                MMA16816(acc[ma], ah, bl);
            }
        }
    }

    #pragma unroll
    for (int ma=0;ma<2;ma++){
        int r0 = ma*16 + (lane>>2);
        int r1 = r0 + 8;
        int px = px0 + wn*8 + ((lane&3)<<1);
        if (r0 < 18){
            float bb = b_off[r0];
            *(float2*)&g_offset[((size_t)(b*18 + r0))*PP + px] =
                make_float2(acc[ma][0]+bb, acc[ma][1]+bb);
        }
        if (r1 < 18){
            float bb = b_off[r1];
            *(float2*)&g_offset[((size_t)(b*18 + r1))*PP + px] =
                make_float2(acc[ma][2]+bb, acc[ma][3]+bb);
        }
    }
}

// ---------------- deformable conv via mma (unchanged) ----------------
#define DSM_AH 18432
#define DSM_AL (18432+9216)
#define DSM_BH 36864
#define DSM_BL 55296
#define DSM_TOTAL 73728

__global__ __launch_bounds__(256) void deform_mma(const float* __restrict__ x){
    extern __shared__ char sm[];
    int*   s_y0 = (int*)sm;
    int*   s_x0 = (int*)(sm + 4608);
    float* s_wy = (float*)(sm + 9216);
    float* s_wx = (float*)(sm + 13824);
    uint32_t su = smem_u32(sm);
    int t = threadIdx.x, lane = t & 31, wid = t >> 5;
    int wm = wid >> 2, wn = wid & 3;
    int px0 = blockIdx.x*128;
    int g   = blockIdx.y;
    int b   = blockIdx.z;

    for (int e=t; e<1152; e+=256){
        int k = e >> 7, pxl = e & 127;
        int px = px0 + pxl;
        int y = px >> 6, xc = px & 63;
        float dy = g_offset[(b*18 + 2*k  )*PP + px];
        float dx = g_offset[(b*18 + 2*k+1)*PP + px];
        float py  = (float)y  + (float)(k/3 - 1) + dy;
        float pxx = (float)xc + (float)(k%3 - 1) + dx;
        float fy = floorf(py), fx = floorf(pxx);
        s_y0[e] = (int)fy; s_x0[e] = (int)fx;
        s_wy[e] = py - fy; s_wx[e] = pxx - fx;
    }
    __syncthreads();

    float acc[2][4][4];
    #pragma unroll
    for (int i=0;i<2;i++)
        #pragma unroll
        for (int j=0;j<4;j++)
            #pragma unroll
            for (int q=0;q<4;q++) acc[i][j][q]=0.f;

    const float* xb = x + (size_t)(b*CC + g*64)*PP;
    int l16 = lane & 15;
    uint32_t aoff_base = (uint32_t)((wm*32 + (lane & 15))*144 + ((lane >> 4) << 3)*2);
    uint32_t boff_base = (uint32_t)((wn*32 + (l16 & 7))*144 + ((l16 >> 3) << 3)*2);

    for (int k=0;k<9;k++){
        if (k) __syncthreads();
        {
            const __nv_bfloat16* sh = g_wdefhi + (size_t)(g*64*9 + k)*64;
            const __nv_bfloat16* sl = g_wdeflo + (size_t)(g*64*9 + k)*64;
            #pragma unroll
            for (int i=0;i<2;i++){
                int e = t + i*256;
                int r = e >> 3, c = e & 7;
                *(uint4*)(sm + DSM_AH + r*144 + c*16) = *(const uint4*)(sh + (size_t)r*576 + c*8);
                *(uint4*)(sm + DSM_AL + r*144 + c*16) = *(const uint4*)(sl + (size_t)r*576 + c*8);
            }
        }
        {
            int pxl = t & 127;
            int cg0 = (t >> 7) << 5;
            int ce = k*128 + pxl;
            int y0 = s_y0[ce], x0 = s_x0[ce];
            float wy = s_wy[ce], wx = s_wx[ce];
            float w00 = (1.f-wy)*(1.f-wx);
            float w01 = (1.f-wy)*wx;
            float w10 = wy*(1.f-wx);
            float w11 = wy*wx;
            bool vy0 = (y0 >= 0) && (y0 < HH);
            bool vy1 = (y0 >= -1) && (y0 < HH-1);
            bool vx0 = (x0 >= 0) && (x0 < WW);
            bool vx1 = (x0 >= -1) && (x0 < WW-1);
            float m00 = (vy0 && vx0) ? w00 : 0.f;
            float m01 = (vy0 && vx1) ? w01 : 0.f;
            float m10 = (vy1 && vx0) ? w10 : 0.f;
            float m11 = (vy1 && vx1) ? w11 : 0.f;
            int cy0 = min(max(y0,0),HH-1), cy1 = min(max(y0+1,0),HH-1);
            int cx0 = min(max(x0,0),WW-1), cx1 = min(max(x0+1,0),WW-1);
            int i00 = cy0*WW+cx0, i01 = cy0*WW+cx1;
            int i10 = cy1*WW+cx0, i11 = cy1*WW+cx1;
            char* bh = sm + DSM_BH + pxl*144 + cg0*2;
            char* bl = sm + DSM_BL + pxl*144 + cg0*2;
            #pragma unroll 4
            for (int j=0;j<32;j+=2){
                const float* p0 = xb + (size_t)(cg0+j)*PP;
                const float* p1 = p0 + PP;
                float v0 = p0[i00]*m00 + p0[i01]*m01 + p0[i10]*m10 + p0[i11]*m11;
                float v1 = p1[i00]*m00 + p1[i01]*m01 + p1[i10]*m10 + p1[i11]*m11;
                __nv_bfloat16 h0,l0,h1,l1;
                split2(v0,h0,l0); split2(v1,h1,l1);
                *(uint32_t*)(bh + j*2) = (uint32_t)__bfloat16_as_ushort(h0) | ((uint32_t)__bfloat16_as_ushort(h1)<<16);
                *(uint32_t*)(bl + j*2) = (uint32_t)__bfloat16_as_ushort(l0) | ((uint32_t)__bfloat16_as_ushort(l1)<<16);
            }
        }
        __syncthreads();
        #pragma unroll
        for (int ks=0;ks<4;ks++){
            uint32_t bh[4][2], bl[4][2];
            #pragma unroll
            for (int na=0;na<4;na++){
                uint32_t boff = boff_base + (uint32_t)(na*8*144 + ks*32);
                LDSM_X2(bh[na], su + DSM_BH + boff);
                LDSM_X2(bl[na], su + DSM_BL + boff);
            }
            #pragma unroll
            for (int ma=0;ma<2;ma++){
                uint32_t aoff = aoff_base + (uint32_t)(ma*16*144 + ks*32);
                uint32_t ah[4], al[4];
                LDSM_X4(ah, su + DSM_AH + aoff);
                LDSM_X4(al, su + DSM_AL + aoff);
                #pragma unroll
                for (int na=0;na<4;na++){
                    MMA16816(acc[ma][na], ah, bh[na]);
                    MMA16816(acc[ma][na], al, bh[na]);
                    MMA16816(acc[ma][na], ah, bl[na]);
                }
            }
        }
    }

    __syncthreads();
    #pragma unroll
    for (int ma=0;ma<2;ma++){
        int r0 = wm*32 + ma*16 + (lane>>2);
        int r1 = r0 + 8;
        #pragma unroll
        for (int na=0;na<4;na++){
            int px = wn*32 + na*8 + ((lane&3)<<1);
            __nv_bfloat16 h,l;
            split2(acc[ma][na][0],h,l);
            *(__nv_bfloat16*)(sm + px*144 + r0*2) = h;
            *(__nv_bfloat16*)(sm + 18432 + px*144 + r0*2) = l;
            split2(acc[ma][na][1],h,l);
            *(__nv_bfloat16*)(sm + (px+1)*144 + r0*2) = h;
            *(__nv_bfloat16*)(sm + 18432 + (px+1)*144 + r0*2) = l;
            split2(acc[ma][na][2],h,l);
            *(__nv_bfloat16*)(sm + px*144 + r1*2) = h;
            *(__nv_bfloat16*)(sm + 18432 + px*144 + r1*2) = l;
            split2(acc[ma][na][3],h,l);
            *(__nv_bfloat16*)(sm + (px+1)*144 + r1*2) = h;
            *(__nv_bfloat16*)(sm + 18432 + (px+1)*144 + r1*2) = l;
        }
    }
    __syncthreads();
    #pragma unroll
    for (int i=0;i<4;i++){
        int e = t + i*256;
        int r = e >> 3, c8 = e & 7;
        size_t o = ((size_t)(b*PP) + px0 + r)*512 + g*64 + c8*8;
        *(uint4*)(g_Bchi + o) = *(const uint4*)(sm + r*144 + c8*16);
        *(uint4*)(g_Bclo + o) = *(const uint4*)(sm + 18432 + r*144 + c8*16);
    }
}

// ---------------- generic mma GEMM (cp.async 2-stage) 128co x 128px ----------------
#define T_BYTES  (128*144)              // 18432
#define G_STAGE  (4*T_BYTES)            // 73728
#define SMEM_GEMM (2*G_STAGE)           // 147456

template<int K>
__device__ __forceinline__ void gemm_copy(uint32_t su, int s, int c, int t,
    const __nv_bfloat16* Ab, const __nv_bfloat16* Alb,
    const __nv_bfloat16* Bb, const __nv_bfloat16* Blb){
    uint32_t base = su + s*G_STAGE;
    #pragma unroll
    for (int i=0;i<4;i++){
        int e = t + i*256;
        int r = e >> 3, c8 = e & 7;
        uint32_t so = (uint32_t)(r*144 + c8*16);
        size_t go = (size_t)r*K + c*64 + c8*8;
        CP16(base + so,             Ab  + go);
        CP16(base + T_BYTES + so,   Alb + go);
        CP16(base + 2*T_BYTES + so, Bb  + go);
        CP16(base + 3*T_BYTES + so, Blb + go);
    }
}

template<int MODE>
__global__ __launch_bounds__(256) void gemm_mma(const float* __restrict__ bias,
                                                const float* __restrict__ gamma,
                                                const float* __restrict__ beta,
                                                const float* __restrict__ mean,
                                                const float* __restrict__ var,
                                                const float* __restrict__ resid,
                                                float* __restrict__ outp){
    constexpr int K = (MODE==0) ? 512 : (MODE==1 ? 64 : 256);
    constexpr int CHUNKS = K/64;
    extern __shared__ char smem[];
    uint32_t su = smem_u32(smem);
    int t    = threadIdx.x;
    int lane = t & 31;
    int wid  = t >> 5;
    int wm   = wid >> 2;
    int wn   = wid & 3;
    int px0  = blockIdx.x*128;
    int co0  = blockIdx.y*128;
    int b    = blockIdx.z;

    const __nv_bfloat16* Ahi = (MODE==0) ? g_Achi : (MODE==1 ? g_Ag2hi : g_Aohi);
    const __nv_bfloat16* Alo = (MODE==0) ? g_Aclo : (MODE==1 ? g_Ag2lo : g_Aolo);
    const __nv_bfloat16* Bhi = (MODE==0) ? g_Bchi : (MODE==1 ? g_Bahi : g_Bohi);
    const __nv_bfloat16* Blo = (MODE==0) ? g_Bclo : (MODE==1 ? g_Balo : g_Bolo);

    const __nv_bfloat16* Ab  = Ahi + (size_t)co0*K;
    const __nv_bfloat16* Alb = Alo + (size_t)co0*K;
    const __nv_bfloat16* Bb  = Bhi + ((size_t)(b*PP) + px0)*K;
    const __nv_bfloat16* Blb = Blo + ((size_t)(b*PP) + px0)*K;

    float acc[4][4][4];
    #pragma unroll
    for (int i=0;i<4;i++)
        #pragma unroll
        for (int j=0;j<4;j++)
            #pragma unroll
            for (int q=0;q<4;q++) acc[i][j][q] = 0.f;

    int l16 = lane & 15;
    uint32_t aoff_base = (uint32_t)((wm*64 + (lane & 15))*144 + ((lane >> 4) << 3)*2);
    uint32_t boff_base = (uint32_t)((wn*32 + (l16 & 7))*144 + ((l16 >> 3) << 3)*2);

    gemm_copy<K>(su, 0, 0, t, Ab, Alb, Bb, Blb);
    CP_COMMIT();

    for (int c = 0; c < CHUNKS; c++){
        CP_WAIT0();
        __syncthreads();
        if (c+1 < CHUNKS){ gemm_copy<K>(su, (c+1)&1, c+1, t, Ab, Alb, Bb, Blb); CP_COMMIT(); }
        uint32_t sb = su + (c&1)*G_STAGE;
        #pragma unroll
        for (int ks = 0; ks < 4; ks++){
            uint32_t bh[4][2], bl[4][2];
            #pragma unroll
            for (int na=0;na<4;na++){
                uint32_t boff = boff_base + (uint32_t)(na*8*144 + ks*32);
                LDSM_X2(bh[na], sb + 2*T_BYTES + boff);
                LDSM_X2(bl[na], sb + 3*T_BYTES + boff);
            }
            #pragma unroll
            for (int ma=0;ma<4;ma++){
                uint32_t aoff = aoff_base + (uint32_t)(ma*16*144 + ks*32);
                uint32_t ah[4], al[4];
                LDSM_X4(ah, sb + aoff);
                LDSM_X4(al, sb + T_BYTES + aoff);
                #pragma unroll
                for (int na=0;na<4;na++){
                    MMA16816(acc[ma][na], ah, bh[na]);
                    MMA16816(acc[ma][na], al, bh[na]);
                    MMA16816(acc[ma][na], ah, bl[na]);
                }
            }
        }
    }

    if (MODE == 2){
        #pragma unroll
        for (int ma=0;ma<4;ma++){
            int r0 = co0 + wm*64 + ma*16 + (lane>>2);
            int r1 = r0 + 8;
            float bb0 = bias[r0], bb1 = bias[r1];
            float iv0 = gamma[r0]*rsqrtf(var[r0]+1e-5f), sh0 = beta[r0]-mean[r0]*iv0;
            float iv1 = gamma[r1]*rsqrtf(var[r1]+1e-5f), sh1 = beta[r1]-mean[r1]*iv1;
            #pragma unroll
            for (int na=0;na<4;na++){
                int px = px0 + wn*32 + na*8 + ((lane&3)<<1);
                size_t i0 = ((size_t)(b*CC + r0))*PP + px;
                size_t i1 = ((size_t)(b*CC + r1))*PP + px;
                float2 rv0 = *(const float2*)&resid[i0];
                float2 rv1 = *(const float2*)&resid[i1];
                float v0 = (acc[ma][na][0]+bb0)*iv0 + sh0;
                float v1 = (acc[ma][na][1]+bb0)*iv0 + sh0;
                float v2 = (acc[ma][na][2]+bb1)*iv1 + sh1;
                float v3 = (acc[ma][na][3]+bb1)*iv1 + sh1;
                *(float2*)&outp[i0] = make_float2(rv0.x + v0*sigm(v0), rv0.y + v1*sigm(v1));
                *(float2*)&outp[i1] = make_float2(rv1.x + v2*sigm(v2), rv1.y + v3*sigm(v3));
            }
        }
        return;
    }

    __syncthreads();
    #pragma unroll
    for (int ma=0;ma<4;ma++){
        int r0 = wm*64 + ma*16 + (lane>>2);
        int r1 = r0 + 8;
        int gr0 = co0 + r0, gr1 = co0 + r1;
        float bb0=0.f, bb1=0.f;
        if (MODE==1){ bb0 = bias[gr0]; bb1 = bias[gr1]; }
        #pragma unroll
        for (int na=0;na<4;na++){
            int px = wn*32 + na*8 + ((lane&3)<<1);
            float d0 = acc[ma][na][0], d1 = acc[ma][na][1];
            float d2 = acc[ma][na][2], d3 = acc[ma][na][3];
            float v0, v1, v2, v3;
            if (MODE==0){
                size_t i0 = ((size_t)(b*CC + gr0))*PP + px0 + px;
                size_t i1 = ((size_t)(b*CC + gr1))*PP + px0 + px;
                *(float2*)&g_xdense[i0] = make_float2(d0, d1);
                *(float2*)&g_xdense[i1] = make_float2(d2, d3);
                v0 = d0; v1 = d1; v2 = d2; v3 = d3;
            } else {
                size_t i0 = ((size_t)(b*CC + gr0))*PP + px0 + px;
                size_t i1 = ((size_t)(b*CC + gr1))*PP + px0 + px;
                float2 x0 = *(const float2*)&g_xdense[i0];
                float2 x1 = *(const float2*)&g_xdense[i1];
                v0 = x0.x * sigm(d0+bb0);
                v1 = x0.y * sigm(d1+bb0);
                v2 = x1.x * sigm(d2+bb1);
                v3 = x1.y * sigm(d3+bb1);
            }
            __nv_bfloat16 h,l;
            split2(v0,h,l);
            *(__nv_bfloat16*)(smem + px*272 + r0*2) = h;
            *(__nv_bfloat16*)(smem + 34816 + px*272 + r0*2) = l;
            split2(v1,h,l);
            *(__nv_bfloat16*)(smem + (px+1)*272 + r0*2) = h;
            *(__nv_bfloat16*)(smem + 34816 + (px+1)*272 + r0*2) = l;
            split2(v2,h,l);
            *(__nv_bfloat16*)(smem + px*272 + r1*2) = h;
            *(__nv_bfloat16*)(smem + 34816 + px*272 + r1*2) = l;
            split2(v3,h,l);
            *(__nv_bfloat16*)(smem + (px+1)*272 + r1*2) = h;
            *(__nv_bfloat16*)(smem + 34816 + (px+1)*272 + r1*2) = l;
        }
    }
    __syncthreads();
    {
        __nv_bfloat16* Dh = (MODE==0) ? g_Bxhi : g_Bohi;
        __nv_bfloat16* Dl = (MODE==0) ? g_Bxlo : g_Bolo;
        #pragma unroll
        for (int i=0;i<8;i++){
            int e = t + i*256;
            int r = e >> 4, c16 = e & 15;
            size_t o = ((size_t)(b*PP) + px0 + r)*256 + co0 + c16*8;
            *(uint4*)(Dh + o) = *(const uint4*)(smem + r*272 + c16*16);
            *(uint4*)(Dl + o) = *(const uint4*)(smem + 34816 + r*272 + c16*16);
        }
    }
}

// ---------------- g1 3x3 conv implicit GEMM (cp.async 2-stage) -> g_Ba ----------------
// stage: AH 0 (9216) | AL 9216 | BH 18432 (18432) | BL 36864 ; stage = 55296
#define G1_STAGE 55296
#define G1_TOTAL (2*G1_STAGE)

__device__ __forceinline__ void g1_copy(uint32_t su, char* smc, int s, int c, int t, int b, int px0){
    int k = c >> 2, sub = c & 3;
    int dy = k/3 - 1, dx = k%3 - 1;
    int off = dy*WW + dx;
    uint32_t base = su + s*G1_STAGE;
    #pragma unroll
    for (int i=0;i<2;i++){
        int e = t + i*256;
        int r = e >> 3, c8 = e & 7;
        uint32_t so = (uint32_t)(r*144 + c8*16);
        CP16(base + so,        g_w1hi + (size_t)r*2304 + k*256 + sub*64 + c8*8);
        CP16(base + 9216 + so, g_w1lo + (size_t)r*2304 + k*256 + sub*64 + c8*8);
    }
    #pragma unroll
    for (int i=0;i<4;i++){
        int e = t + i*256;
        int r = e >> 3, c8 = e & 7;
        uint32_t so = (uint32_t)(r*144 + c8*16);
        int px = px0 + r;
        int y = px >> 6, xc = px & 63;
        int yy = y + dy, xx = xc + dx;
        bool valid = ((unsigned)yy < HH) && ((unsigned)xx < WW);
        if (valid){
            size_t rb = ((size_t)(b*PP) + px + off)*256 + sub*64 + c8*8;
            CP16(base + 18432 + so, g_Bxhi + rb);
            CP16(base + 36864 + so, g_Bxlo + rb);
        } else {
            *(uint4*)(smc + s*G1_STAGE + 18432 + so) = make_uint4(0,0,0,0);
            *(uint4*)(smc + s*G1_STAGE + 36864 + so) = make_uint4(0,0,0,0);
        }
    }
}

__global__ __launch_bounds__(256) void g1_mma(const float* __restrict__ bias,
                                              const float* __restrict__ gamma,
                                              const float* __restrict__ beta,
                                              const float* __restrict__ mean,
                                              const float* __restrict__ var){
    extern __shared__ char sm[];
    uint32_t su = smem_u32(sm);
    int t = threadIdx.x, lane = t & 31, wid = t >> 5;
    int wm = wid >> 2, wn = wid & 3;
    int px0 = blockIdx.x*128;
    int b   = blockIdx.y;

    float acc[2][4][4];
    #pragma unroll
    for (int i=0;i<2;i++)
        #pragma unroll
        for (int j=0;j<4;j++)
            #pragma unroll
            for (int q=0;q<4;q++) acc[i][j][q]=0.f;

    int l16 = lane & 15;
    uint32_t aoff_base = (uint32_t)((wm*32 + (lane & 15))*144 + ((lane >> 4) << 3)*2);
    uint32_t boff_base = (uint32_t)((wn*32 + (l16 & 7))*144 + ((l16 >> 3) << 3)*2);

    g1_copy(su, sm, 0, 0, t, b, px0);
    CP_COMMIT();

    for (int c = 0; c < 36; c++){
        CP_WAIT0();
        __syncthreads();
        if (c+1 < 36){ g1_copy(su, sm, (c+1)&1, c+1, t, b, px0); CP_COMMIT(); }
        uint32_t sb = su + (c&1)*G1_STAGE;
        #pragma unroll
        for (int ks=0;ks<4;ks++){
            uint32_t bh[4][2], bl[4][2];
            #pragma unroll
            for (int na=0;na<4;na++){
                uint32_t boff = boff_base + (uint32_t)(na*8*144 + ks*32);
                LDSM_X2(bh[na], sb + 18432 + boff);
                LDSM_X2(bl[na], sb + 36864 + boff);
            }
            #pragma unroll
            for (int ma=0;ma<2;ma++){
                uint32_t aoff = aoff_base + (uint32_t)(ma*16*144 + ks*32);
                uint32_t ah[4], al[4];
                LDSM_X4(ah, sb + aoff);
                LDSM_X4(al, sb + 9216 + aoff);
                #pragma unroll
                for (int na=0;na<4;na++){
                    MMA16816(acc[ma][na], ah, bh[na]);
                    MMA16816(acc[ma][na], al, bh[na]);
                    MMA16816(acc[ma][na], ah, bl[na]);
                }
            }
        }
    }

    __syncthreads();
    #pragma unroll
    for (int ma=0;ma<2;ma++){
        int r0 = wm*32 + ma*16 + (lane>>2);
        int r1 = r0 + 8;
        float bb0 = bias[r0], bb1 = bias[r1];
        float iv0 = gamma[r0]*rsqrtf(var[r0]+1e-5f), sh0 = beta[r0]-mean[r0]*iv0;
        float iv1 = gamma[r1]*rsqrtf(var[r1]+1e-5f), sh1 = beta[r1]-mean[r1]*iv1;
        #pragma unroll
        for (int na=0;na<4;na++){
            int px = wn*32 + na*8 + ((lane&3)<<1);
            float v0 = (acc[ma][na][0]+bb0)*iv0 + sh0; v0 = v0*sigm(v0);
            float v1 = (acc[ma][na][1]+bb0)*iv0 + sh0; v1 = v1*sigm(v1);
            float v2 = (acc[ma][na][2]+bb1)*iv1 + sh1; v2 = v2*sigm(v2);
            float v3 = (acc[ma][na][3]+bb1)*iv1 + sh1; v3 = v3*sigm(v3);
            __nv_bfloat16 h,l;
            split2(v0,h,l);
            *(__nv_bfloat16*)(sm + px*144 + r0*2) = h;
            *(__nv_bfloat16*)(sm + 18432 + px*144 + r0*2) = l;
            split2(v1,h,l);
            *(__nv_bfloat16*)(sm + (px+1)*144 + r0*2) = h;
            *(__nv_bfloat16*)(sm + 18432 + (px+1)*144 + r0*2) = l;
            split2(v2,h,l);
            *(__nv_bfloat16*)(sm + px*144 + r1*2) = h;
            *(__nv_bfloat16*)(sm + 18432 + px*144 + r1*2) = l;
            split2(v3,h,l);
            *(__nv_bfloat16*)(sm + (px+1)*144 + r1*2) = h;
            *(__nv_bfloat16*)(sm + 18432 + (px+1)*144 + r1*2) = l;
        }
    }
    __syncthreads();
    #pragma unroll
    for (int i=0;i<4;i++){
        int e = t + i*256;
        int r = e >> 3, c8 = e & 7;
        size_t o = ((size_t)(b*PP) + px0 + r)*64 + c8*8;
        *(uint4*)(g_Bahi + o) = *(const uint4*)(sm + r*144 + c8*16);
        *(uint4*)(g_Balo + o) = *(const uint4*)(sm + 18432 + r*144 + c8*16);
    }
}

// ---------------- launch ----------------
extern "C" void kernel_launch(void* const* d_in, const int* in_sizes, int n_in,
                              void* d_out, int out_size){
    const float* x       = (const float*)d_in[0];
    const float* x_prev  = (const float*)d_in[1];
    const float* w_off   = (const float*)d_in[2];
    const float* b_off   = (const float*)d_in[3];
    const float* w_def   = (const float*)d_in[4];
    const float* w_cross = (const float*)d_in[5];
    const float* w_g1    = (const float*)d_in[6];
    const float* b_g1    = (const float*)d_in[7];
    const float* g1_gamma= (const float*)d_in[8];
    const float* g1_beta = (const float*)d_in[9];
    const float* g1_mean = (const float*)d_in[10];
    const float* g1_var  = (const float*)d_in[11];
    const float* w_g2    = (const float*)d_in[12];
    const float* b_g2    = (const float*)d_in[13];
    const float* w_out   = (const float*)d_in[14];
    const float* b_out   = (const float*)d_in[15];
    const float* o_gamma = (const float*)d_in[16];
    const float* o_beta  = (const float*)d_in[17];
    const float* o_mean  = (const float*)d_in[18];
    const float* o_var   = (const float*)d_in[19];
    float* out = (float*)d_out;

    cudaFuncSetAttribute(gemm_mma<0>, cudaFuncAttributeMaxDynamicSharedMemorySize, SMEM_GEMM);
    cudaFuncSetAttribute(gemm_mma<1>, cudaFuncAttributeMaxDynamicSharedMemorySize, SMEM_GEMM);
    cudaFuncSetAttribute(gemm_mma<2>, cudaFuncAttributeMaxDynamicSharedMemorySize, SMEM_GEMM);
    cudaFuncSetAttribute(deform_mma,  cudaFuncAttributeMaxDynamicSharedMemorySize, DSM_TOTAL);
    cudaFuncSetAttribute(g1_mma,      cudaFuncAttributeMaxDynamicSharedMemorySize, G1_TOTAL);
    cudaFuncSetAttribute(offset_mma,  cudaFuncAttributeMaxDynamicSharedMemorySize, OFF_TOTAL);

    split_all<<<2272, 256>>>(w_cross, w_g2, w_out, w_def, w_g1, w_off);
    conv_rows<0><<<dim3(PP/32, 8, BB), 256>>>(x);
    conv_rows<1><<<dim3(PP/32, 8, BB), 256>>>(x_prev);

    offset_mma<<<dim3(PP/64, BB), 256, OFF_TOTAL>>>(b_off);
    deform_mma<<<dim3(PP/128, GG, BB), 256, DSM_TOTAL>>>(x);

    gemm_mma<0><<<dim3(PP/128, 2, BB), 256, SMEM_GEMM>>>(nullptr,nullptr,nullptr,nullptr,nullptr,nullptr,nullptr);
    g1_mma<<<dim3(PP/128, BB), 256, G1_TOTAL>>>(b_g1, g1_gamma, g1_beta, g1_mean, g1_var);
    gemm_mma<1><<<dim3(PP/128, 2, BB), 256, SMEM_GEMM>>>(b_g2,nullptr,nullptr,nullptr,nullptr,nullptr,nullptr);
    gemm_mma<2><<<dim3(PP/128, 2, BB), 256, SMEM_GEMM>>>(b_out, o_gamma, o_beta, o_mean, o_var, x, out);
}

// round 7
// speedup vs baseline: 3.2260x; 1.0626x over previous
#include <cuda_runtime.h>
#include <cuda_bf16.h>
#include <math.h>
#include <stdint.h>

#define BB 4
#define CC 256
#define HH 64
#define WW 64
#define PP (HH*WW)
#define GG 4

// ---------------- device scratch ----------------
__device__ float g_offset[BB*18*PP];
__device__ float g_xdense[BB*CC*PP];

// bf16 hi/lo weights
__device__ __nv_bfloat16 g_Achi[256*512], g_Aclo[256*512];         // w_cross
__device__ __nv_bfloat16 g_Ag2hi[256*64], g_Ag2lo[256*64];         // w_g2
__device__ __nv_bfloat16 g_Aohi[256*256], g_Aolo[256*256];         // w_out
__device__ __nv_bfloat16 g_wdefhi[GG*64*9*64], g_wdeflo[GG*64*9*64];   // [g][co][k][cg]
__device__ __nv_bfloat16 g_w1hi[64*9*256],    g_w1lo[64*9*256];        // [co][k][ci]
__device__ __nv_bfloat16 g_woffhi[32*9*256],  g_wofflo[32*9*256];      // [co pad32][k][ci]
// bf16 hi/lo activation B-operands [px][ch]
__device__ __nv_bfloat16 g_Bchi[(size_t)BB*PP*512], g_Bclo[(size_t)BB*PP*512];   // cross in
__device__ __nv_bfloat16 g_Bxhi[(size_t)BB*PP*256], g_Bxlo[(size_t)BB*PP*256];   // xdense
__device__ __nv_bfloat16 g_Bahi[(size_t)BB*PP*64],  g_Balo[(size_t)BB*PP*64];    // g1 out
__device__ __nv_bfloat16 g_Bohi[(size_t)BB*PP*256], g_Bolo[(size_t)BB*PP*256];   // xdense*attn
__device__ __nv_bfloat16 g_Bxinhi[(size_t)BB*PP*256], g_Bxinlo[(size_t)BB*PP*256]; // x

__device__ __forceinline__ float sigm(float v){ return 1.0f/(1.0f+expf(-v)); }

__device__ __forceinline__ void split2(float v, __nv_bfloat16 &h, __nv_bfloat16 &l){
    h = __float2bfloat16(v);
    l = __float2bfloat16(v - __bfloat162float(h));
}

__device__ __forceinline__ uint32_t smem_u32(const void* p){
    uint32_t a;
    asm("{ .reg .u64 tmp; cvta.to.shared.u64 tmp, %1; cvt.u32.u64 %0, tmp; }" : "=r"(a) : "l"(p));
    return a;
}

#define LDSM_X4(r, addr) \
    asm volatile("ldmatrix.sync.aligned.m8n8.x4.shared.b16 {%0,%1,%2,%3}, [%4];" \
        : "=r"((r)[0]), "=r"((r)[1]), "=r"((r)[2]), "=r"((r)[3]) : "r"(addr))
#define LDSM_X2(r, addr) \
    asm volatile("ldmatrix.sync.aligned.m8n8.x2.shared.b16 {%0,%1}, [%2];" \
        : "=r"((r)[0]), "=r"((r)[1]) : "r"(addr))
#define MMA16816(d, a, bfr) \
    asm volatile("mma.sync.aligned.m16n8k16.row.col.f32.bf16.bf16.f32 " \
        "{%0,%1,%2,%3}, {%4,%5,%6,%7}, {%8,%9}, {%0,%1,%2,%3};" \
        : "+f"((d)[0]), "+f"((d)[1]), "+f"((d)[2]), "+f"((d)[3]) \
        : "r"((a)[0]), "r"((a)[1]), "r"((a)[2]), "r"((a)[3]), "r"((bfr)[0]), "r"((bfr)[1]))

#define CP16(dst, src) \
    asm volatile("cp.async.cg.shared.global [%0], [%1], 16;" :: "r"(dst), "l"(src))
#define CP_COMMIT() asm volatile("cp.async.commit_group;" ::: "memory")
#define CP_WAIT0()  asm volatile("cp.async.wait_group 0;" ::: "memory")

// ---------------- merged weight split ----------------
__global__ void split_all(const float* __restrict__ w_cross,
                          const float* __restrict__ w_g2,
                          const float* __restrict__ w_out,
                          const float* __restrict__ w_def,
                          const float* __restrict__ w_g1,
                          const float* __restrict__ w_off){
    int id = blockIdx.x*256 + threadIdx.x;
    if (id < 131072){
        split2(w_cross[id], g_Achi[id], g_Aclo[id]); return;
    }
    id -= 131072;
    if (id < 16384){
        split2(w_g2[id], g_Ag2hi[id], g_Ag2lo[id]); return;
    }
    id -= 16384;
    if (id < 65536){
        split2(w_out[id], g_Aohi[id], g_Aolo[id]); return;
    }
    id -= 65536;
    if (id < 147456){
        int cg = id & 63;
        int r  = id >> 6;
        int k  = r % 9;
        int r2 = r / 9;
        int co = r2 & 63;
        int g  = r2 >> 6;
        split2(w_def[((g*64 + co)*64 + cg)*9 + k], g_wdefhi[id], g_wdeflo[id]);
        return;
    }
    id -= 147456;
    if (id < 147456){
        int ci = id & 255;
        int r  = id >> 8;
        int k  = r % 9;
        int co = r / 9;
        split2(w_g1[(co*256 + ci)*9 + k], g_w1hi[id], g_w1lo[id]);
        return;
    }
    id -= 147456;
    if (id < 73728){
        int ci = id & 255;
        int r  = id >> 8;
        int k  = r % 9;
        int co = r / 9;
        float v = (co < 18) ? w_off[(co*256 + ci)*9 + k] : 0.f;
        split2(v, g_woffhi[id], g_wofflo[id]);
    }
}

// ---------------- converter: [ch][px] fp32 -> [px][ch] hi/lo ----------------
template<int DST>
__global__ __launch_bounds__(256) void conv_rows(const float* __restrict__ src){
    __shared__ float tile[32][33];
    int px0 = blockIdx.x*32;
    int ch0 = blockIdx.y*32;
    int b   = blockIdx.z;
    int t   = threadIdx.x;
    #pragma unroll
    for (int i=0;i<4;i++){
        int e = t + i*256;
        int r = e >> 5, c = e & 31;
        tile[r][c] = src[((size_t)(b*256+ch0+r))*PP + px0 + c];
    }
    __syncthreads();
    #pragma unroll
    for (int i=0;i<4;i++){
        int e = t + i*256;
        int r = e >> 5, c = e & 31;
        __nv_bfloat16 h, l;
        split2(tile[c][r], h, l);
        if (DST==0){
            size_t o = ((size_t)(b*PP) + px0 + r)*256 + ch0 + c;
            g_Bxinhi[o]=h; g_Bxinlo[o]=l;
        } else {
            size_t o = ((size_t)(b*PP) + px0 + r)*512 + 256 + ch0 + c;
            g_Bchi[o]=h; g_Bclo[o]=l;
        }
    }
}

// ================= 3x3 conv implicit GEMM with halo-resident B =================
// B tile: pixel rows [px0-64, px0+192) = 256 rows x 64ch (stride 144) + zero row @256.
// Per tap k, each lane addresses its shifted row directly (ldmatrix per-lane addr).
// CO=32/MODE=0: offset conv (B = g_Bxin, out = g_offset+bias)
// CO=64/MODE=1: g1 conv     (B = g_Bx,   out = bn+silu -> g_Ba)
#define CB_BSZ 37008           // 257 rows * 144
template<int CO, int MODE>
__global__ __launch_bounds__(256) void conv3_mma(const float* __restrict__ p0,
                                                 const float* __restrict__ p1,
                                                 const float* __restrict__ p2,
                                                 const float* __restrict__ p3,
                                                 const float* __restrict__ p4){
    constexpr int ASZ  = CO*144;
    constexpr int BOFF = 4*ASZ;
    constexpr int NWN  = (CO==64) ? 4 : 8;
    constexpr int PXW  = 128/NWN;
    constexpr int NA   = PXW/8;
    extern __shared__ char sm[];
    uint32_t su = smem_u32(sm);
    int t = threadIdx.x, lane = t & 31, wid = t >> 5;
    int wm = wid / NWN, wn = wid % NWN;
    int px0 = blockIdx.x*128;
    int b   = blockIdx.y;

    const __nv_bfloat16* Whi = (CO==64) ? g_w1hi : g_woffhi;
    const __nv_bfloat16* Wlo = (CO==64) ? g_w1lo : g_wofflo;
    const __nv_bfloat16* Bhi = (MODE==1) ? g_Bxhi : g_Bxinhi;
    const __nv_bfloat16* Blo = (MODE==1) ? g_Bxlo : g_Bxinlo;

    float acc[2][NA][4];
    #pragma unroll
    for (int i=0;i<2;i++)
        #pragma unroll
        for (int j=0;j<NA;j++)
            #pragma unroll
            for (int q=0;q<4;q++) acc[i][j][q]=0.f;

    int l16 = lane & 15;
    uint32_t aoff_base = (uint32_t)(((CO==64 ? wm*32 : 0) + (lane & 15))*144 + ((lane >> 4) << 3)*2);
    uint32_t bcol = (uint32_t)((l16 >> 3)*16);
    int rr[NA], ry[NA], rxc[NA];
    #pragma unroll
    for (int na=0;na<NA;na++){
        int r = wn*PXW + na*8 + (l16 & 7);
        rr[na] = r;
        int px = px0 + r;
        ry[na]  = px >> 6;
        rxc[na] = px & 63;
    }

    // zero row @256 (both zones)
    if (t < 9)        *(uint4*)(sm + BOFF + 256*144 + t*16) = make_uint4(0,0,0,0);
    else if (t < 18)  *(uint4*)(sm + BOFF + CB_BSZ + 256*144 + (t-9)*16) = make_uint4(0,0,0,0);

    for (int sub=0; sub<4; sub++){
        __syncthreads();
        // fill B: 256 rows x 8 chunks (hi+lo)
        #pragma unroll
        for (int i=0;i<8;i++){
            int e = t + i*256;
            int rt = e >> 3, c8 = e & 7;
            int p = px0 - 64 + rt;
            if ((unsigned)p < (unsigned)PP){
                size_t rb = ((size_t)(b*PP) + p)*256 + sub*64 + c8*8;
                uint32_t so = (uint32_t)(rt*144 + c8*16);
                CP16(su + BOFF + so,          Bhi + rb);
                CP16(su + BOFF + CB_BSZ + so, Blo + rb);
            }
        }
        // fill A(k=0) stage 0
        #pragma unroll
        for (int i=0;i<CO/32;i++){
            int e = t + i*256;
            int r = e >> 3, c8 = e & 7;
            uint32_t so = (uint32_t)(r*144 + c8*16);
            size_t go = (size_t)r*2304 + 0*256 + sub*64 + c8*8;
            CP16(su + so,       Whi + go);
            CP16(su + ASZ + so, Wlo + go);
        }
        CP_COMMIT();

        for (int k=0;k<9;k++){
            CP_WAIT0();
            __syncthreads();
            if (k < 8){
                int st = (k+1) & 1;
                #pragma unroll
                for (int i=0;i<CO/32;i++){
                    int e = t + i*256;
                    int r = e >> 3, c8 = e & 7;
                    uint32_t so = (uint32_t)(st*2*ASZ + r*144 + c8*16);
                    size_t go = (size_t)r*2304 + (k+1)*256 + sub*64 + c8*8;
                    CP16(su + so,       Whi + go);
                    CP16(su + ASZ + so, Wlo + go);
                }
                CP_COMMIT();
            }
            int dy = k/3 - 1, dx = k%3 - 1;
            int off = dy*WW + dx;
            uint32_t brow[NA];
            #pragma unroll
            for (int na=0;na<NA;na++){
                int yy = ry[na] + dy, xx = rxc[na] + dx;
                bool v = ((unsigned)yy < HH) && ((unsigned)xx < WW);
                brow[na] = v ? (uint32_t)((rr[na] + 64 + off)*144) : (uint32_t)(256*144);
            }
            uint32_t abase = su + (uint32_t)((k&1)*2*ASZ) + aoff_base;
            #pragma unroll
            for (int ks=0;ks<4;ks++){
                uint32_t bh[NA][2], bl[NA][2];
                #pragma unroll
                for (int na=0;na<NA;na++){
                    uint32_t ba = su + BOFF + brow[na] + bcol + ks*32;
                    LDSM_X2(bh[na], ba);
                    LDSM_X2(bl[na], ba + CB_BSZ);
                }
                #pragma unroll
                for (int ma=0;ma<2;ma++){
                    uint32_t ao = abase + (uint32_t)(ma*16*144 + ks*32);
                    uint32_t ah[4], al[4];
                    LDSM_X4(ah, ao);
                    LDSM_X4(al, ao + ASZ);
                    #pragma unroll
                    for (int na=0;na<NA;na++){
                        MMA16816(acc[ma][na], ah, bh[na]);
                        MMA16816(acc[ma][na], al, bh[na]);
                        MMA16816(acc[ma][na], ah, bl[na]);
                    }
                }
            }
        }
    }

    if (MODE == 0){
        // offset epilogue: +bias -> g_offset (co < 18)
        const float* b_off = p0;
        #pragma unroll
        for (int ma=0;ma<2;ma++){
            int r0 = ma*16 + (lane>>2);
            int r1 = r0 + 8;
            #pragma unroll
            for (int na=0;na<NA;na++){
                int px = px0 + wn*PXW + na*8 + ((lane&3)<<1);
                if (r0 < 18){
                    float bb = b_off[r0];
                    *(float2*)&g_offset[((size_t)(b*18 + r0))*PP + px] =
                        make_float2(acc[ma][na][0]+bb, acc[ma][na][1]+bb);
                }
                if (r1 < 18){
                    float bb = b_off[r1];
                    *(float2*)&g_offset[((size_t)(b*18 + r1))*PP + px] =
                        make_float2(acc[ma][na][2]+bb, acc[ma][na][3]+bb);
                }
            }
        }
    } else {
        // g1 epilogue: bias+bn+silu, transpose -> g_Ba [px][64] hi/lo (stage in A zone)
        const float *bias = p0, *gamma = p1, *beta = p2, *mean = p3, *var = p4;
        __syncthreads();
        #pragma unroll
        for (int ma=0;ma<2;ma++){
            int r0 = wm*32 + ma*16 + (lane>>2);
            int r1 = r0 + 8;
            float bb0 = bias[r0], bb1 = bias[r1];
            float iv0 = gamma[r0]*rsqrtf(var[r0]+1e-5f), sh0 = beta[r0]-mean[r0]*iv0;
            float iv1 = gamma[r1]*rsqrtf(var[r1]+1e-5f), sh1 = beta[r1]-mean[r1]*iv1;
            #pragma unroll
            for (int na=0;na<NA;na++){
                int px = wn*PXW + na*8 + ((lane&3)<<1);
                float v0 = (acc[ma][na][0]+bb0)*iv0 + sh0; v0 = v0*sigm(v0);
                float v1 = (acc[ma][na][1]+bb0)*iv0 + sh0; v1 = v1*sigm(v1);
                float v2 = (acc[ma][na][2]+bb1)*iv1 + sh1; v2 = v2*sigm(v2);
                float v3 = (acc[ma][na][3]+bb1)*iv1 + sh1; v3 = v3*sigm(v3);
                __nv_bfloat16 h,l;
                split2(v0,h,l);
                *(__nv_bfloat16*)(sm + px*144 + r0*2) = h;
                *(__nv_bfloat16*)(sm + 18432 + px*144 + r0*2) = l;
                split2(v1,h,l);
                *(__nv_bfloat16*)(sm + (px+1)*144 + r0*2) = h;
                *(__nv_bfloat16*)(sm + 18432 + (px+1)*144 + r0*2) = l;
                split2(v2,h,l);
                *(__nv_bfloat16*)(sm + px*144 + r1*2) = h;
                *(__nv_bfloat16*)(sm + 18432 + px*144 + r1*2) = l;
                split2(v3,h,l);
                *(__nv_bfloat16*)(sm + (px+1)*144 + r1*2) = h;
                *(__nv_bfloat16*)(sm + 18432 + (px+1)*144 + r1*2) = l;
            }
        }
        __syncthreads();
        #pragma unroll
        for (int i=0;i<4;i++){
            int e = t + i*256;
            int r = e >> 3, c8 = e & 7;
            size_t o = ((size_t)(b*PP) + px0 + r)*64 + c8*8;
            *(uint4*)(g_Bahi + o) = *(const uint4*)(sm + r*144 + c8*16);
            *(uint4*)(g_Balo + o) = *(const uint4*)(sm + 18432 + r*144 + c8*16);
        }
    }
}
#define OFFC_SMEM (4*32*144 + 2*CB_BSZ)   // 92448
#define G1C_SMEM  (4*64*144 + 2*CB_BSZ)   // 110880

// ---------------- deformable conv via mma (unchanged) ----------------
#define DSM_AH 18432
#define DSM_AL (18432+9216)
#define DSM_BH 36864
#define DSM_BL 55296
#define DSM_TOTAL 73728

__global__ __launch_bounds__(256) void deform_mma(const float* __restrict__ x){
    extern __shared__ char sm[];
    int*   s_y0 = (int*)sm;
    int*   s_x0 = (int*)(sm + 4608);
    float* s_wy = (float*)(sm + 9216);
    float* s_wx = (float*)(sm + 13824);
    uint32_t su = smem_u32(sm);
    int t = threadIdx.x, lane = t & 31, wid = t >> 5;
    int wm = wid >> 2, wn = wid & 3;
    int px0 = blockIdx.x*128;
    int g   = blockIdx.y;
    int b   = blockIdx.z;

    for (int e=t; e<1152; e+=256){
        int k = e >> 7, pxl = e & 127;
        int px = px0 + pxl;
        int y = px >> 6, xc = px & 63;
        float dy = g_offset[(b*18 + 2*k  )*PP + px];
        float dx = g_offset[(b*18 + 2*k+1)*PP + px];
        float py  = (float)y  + (float)(k/3 - 1) + dy;
        float pxx = (float)xc + (float)(k%3 - 1) + dx;
        float fy = floorf(py), fx = floorf(pxx);
        s_y0[e] = (int)fy; s_x0[e] = (int)fx;
        s_wy[e] = py - fy; s_wx[e] = pxx - fx;
    }
    __syncthreads();

    float acc[2][4][4];
    #pragma unroll
    for (int i=0;i<2;i++)
        #pragma unroll
        for (int j=0;j<4;j++)
            #pragma unroll
            for (int q=0;q<4;q++) acc[i][j][q]=0.f;

    const float* xb = x + (size_t)(b*CC + g*64)*PP;
    int l16 = lane & 15;
    uint32_t aoff_base = (uint32_t)((wm*32 + (lane & 15))*144 + ((lane >> 4) << 3)*2);
    uint32_t boff_base = (uint32_t)((wn*32 + (l16 & 7))*144 + ((l16 >> 3) << 3)*2);

    for (int k=0;k<9;k++){
        if (k) __syncthreads();
        {
            const __nv_bfloat16* sh = g_wdefhi + (size_t)(g*64*9 + k)*64;
            const __nv_bfloat16* sl = g_wdeflo + (size_t)(g*64*9 + k)*64;
            #pragma unroll
            for (int i=0;i<2;i++){
                int e = t + i*256;
                int r = e >> 3, c = e & 7;
                *(uint4*)(sm + DSM_AH + r*144 + c*16) = *(const uint4*)(sh + (size_t)r*576 + c*8);
                *(uint4*)(sm + DSM_AL + r*144 + c*16) = *(const uint4*)(sl + (size_t)r*576 + c*8);
            }
        }
        {
            int pxl = t & 127;
            int cg0 = (t >> 7) << 5;
            int ce = k*128 + pxl;
            int y0 = s_y0[ce], x0 = s_x0[ce];
            float wy = s_wy[ce], wx = s_wx[ce];
            float w00 = (1.f-wy)*(1.f-wx);
            float w01 = (1.f-wy)*wx;
            float w10 = wy*(1.f-wx);
            float w11 = wy*wx;
            bool vy0 = (y0 >= 0) && (y0 < HH);
            bool vy1 = (y0 >= -1) && (y0 < HH-1);
            bool vx0 = (x0 >= 0) && (x0 < WW);
            bool vx1 = (x0 >= -1) && (x0 < WW-1);
            float m00 = (vy0 && vx0) ? w00 : 0.f;
            float m01 = (vy0 && vx1) ? w01 : 0.f;
            float m10 = (vy1 && vx0) ? w10 : 0.f;
            float m11 = (vy1 && vx1) ? w11 : 0.f;
            int cy0 = min(max(y0,0),HH-1), cy1 = min(max(y0+1,0),HH-1);
            int cx0 = min(max(x0,0),WW-1), cx1 = min(max(x0+1,0),WW-1);
            int i00 = cy0*WW+cx0, i01 = cy0*WW+cx1;
            int i10 = cy1*WW+cx0, i11 = cy1*WW+cx1;
            char* bh = sm + DSM_BH + pxl*144 + cg0*2;
            char* bl = sm + DSM_BL + pxl*144 + cg0*2;
            #pragma unroll 4
            for (int j=0;j<32;j+=2){
                const float* p0 = xb + (size_t)(cg0+j)*PP;
                const float* p1 = p0 + PP;
                float v0 = p0[i00]*m00 + p0[i01]*m01 + p0[i10]*m10 + p0[i11]*m11;
                float v1 = p1[i00]*m00 + p1[i01]*m01 + p1[i10]*m10 + p1[i11]*m11;
                __nv_bfloat16 h0,l0,h1,l1;
                split2(v0,h0,l0); split2(v1,h1,l1);
                *(uint32_t*)(bh + j*2) = (uint32_t)__bfloat16_as_ushort(h0) | ((uint32_t)__bfloat16_as_ushort(h1)<<16);
                *(uint32_t*)(bl + j*2) = (uint32_t)__bfloat16_as_ushort(l0) | ((uint32_t)__bfloat16_as_ushort(l1)<<16);
            }
        }
        __syncthreads();
        #pragma unroll
        for (int ks=0;ks<4;ks++){
            uint32_t bh[4][2], bl[4][2];
            #pragma unroll
            for (int na=0;na<4;na++){
                uint32_t boff = boff_base + (uint32_t)(na*8*144 + ks*32);
                LDSM_X2(bh[na], su + DSM_BH + boff);
                LDSM_X2(bl[na], su + DSM_BL + boff);
            }
            #pragma unroll
            for (int ma=0;ma<2;ma++){
                uint32_t aoff = aoff_base + (uint32_t)(ma*16*144 + ks*32);
                uint32_t ah[4], al[4];
                LDSM_X4(ah, su + DSM_AH + aoff);
                LDSM_X4(al, su + DSM_AL + aoff);
                #pragma unroll
                for (int na=0;na<4;na++){
                    MMA16816(acc[ma][na], ah, bh[na]);
                    MMA16816(acc[ma][na], al, bh[na]);
                    MMA16816(acc[ma][na], ah, bl[na]);
                }
            }
        }
    }

    __syncthreads();
    #pragma unroll
    for (int ma=0;ma<2;ma++){
        int r0 = wm*32 + ma*16 + (lane>>2);
        int r1 = r0 + 8;
        #pragma unroll
        for (int na=0;na<4;na++){
            int px = wn*32 + na*8 + ((lane&3)<<1);
            __nv_bfloat16 h,l;
            split2(acc[ma][na][0],h,l);
            *(__nv_bfloat16*)(sm + px*144 + r0*2) = h;
            *(__nv_bfloat16*)(sm + 18432 + px*144 + r0*2) = l;
            split2(acc[ma][na][1],h,l);
            *(__nv_bfloat16*)(sm + (px+1)*144 + r0*2) = h;
            *(__nv_bfloat16*)(sm + 18432 + (px+1)*144 + r0*2) = l;
            split2(acc[ma][na][2],h,l);
            *(__nv_bfloat16*)(sm + px*144 + r1*2) = h;
            *(__nv_bfloat16*)(sm + 18432 + px*144 + r1*2) = l;
            split2(acc[ma][na][3],h,l);
            *(__nv_bfloat16*)(sm + (px+1)*144 + r1*2) = h;
            *(__nv_bfloat16*)(sm + 18432 + (px+1)*144 + r1*2) = l;
        }
    }
    __syncthreads();
    #pragma unroll
    for (int i=0;i<4;i++){
        int e = t + i*256;
        int r = e >> 3, c8 = e & 7;
        size_t o = ((size_t)(b*PP) + px0 + r)*512 + g*64 + c8*8;
        *(uint4*)(g_Bchi + o) = *(const uint4*)(sm + r*144 + c8*16);
        *(uint4*)(g_Bclo + o) = *(const uint4*)(sm + 18432 + r*144 + c8*16);
    }
}

// ---------------- generic mma GEMM (cp.async 2-stage) 128co x 128px ----------------
#define T_BYTES  (128*144)              // 18432
#define G_STAGE  (4*T_BYTES)            // 73728
#define SMEM_GEMM (2*G_STAGE)           // 147456

template<int K>
__device__ __forceinline__ void gemm_copy(uint32_t su, int s, int c, int t,
    const __nv_bfloat16* Ab, const __nv_bfloat16* Alb,
    const __nv_bfloat16* Bb, const __nv_bfloat16* Blb){
    uint32_t base = su + s*G_STAGE;
    #pragma unroll
    for (int i=0;i<4;i++){
        int e = t + i*256;
        int r = e >> 3, c8 = e & 7;
        uint32_t so = (uint32_t)(r*144 + c8*16);
        size_t go = (size_t)r*K + c*64 + c8*8;
        CP16(base + so,             Ab  + go);
        CP16(base + T_BYTES + so,   Alb + go);
        CP16(base + 2*T_BYTES + so, Bb  + go);
        CP16(base + 3*T_BYTES + so, Blb + go);
    }
}

template<int MODE>
__global__ __launch_bounds__(256) void gemm_mma(const float* __restrict__ bias,
                                                const float* __restrict__ gamma,
                                                const float* __restrict__ beta,
                                                const float* __restrict__ mean,
                                                const float* __restrict__ var,
                                                const float* __restrict__ resid,
                                                float* __restrict__ outp){
    constexpr int K = (MODE==0) ? 512 : (MODE==1 ? 64 : 256);
    constexpr int CHUNKS = K/64;
    extern __shared__ char smem[];
    uint32_t su = smem_u32(smem);
    int t    = threadIdx.x;
    int lane = t & 31;
    int wid  = t >> 5;
    int wm   = wid >> 2;
    int wn   = wid & 3;
    int px0  = blockIdx.x*128;
    int co0  = blockIdx.y*128;
    int b    = blockIdx.z;

    const __nv_bfloat16* Ahi = (MODE==0) ? g_Achi : (MODE==1 ? g_Ag2hi : g_Aohi);
    const __nv_bfloat16* Alo = (MODE==0) ? g_Aclo : (MODE==1 ? g_Ag2lo : g_Aolo);
    const __nv_bfloat16* Bhi = (MODE==0) ? g_Bchi : (MODE==1 ? g_Bahi : g_Bohi);
    const __nv_bfloat16* Blo = (MODE==0) ? g_Bclo : (MODE==1 ? g_Balo : g_Bolo);

    const __nv_bfloat16* Ab  = Ahi + (size_t)co0*K;
    const __nv_bfloat16* Alb = Alo + (size_t)co0*K;
    const __nv_bfloat16* Bb  = Bhi + ((size_t)(b*PP) + px0)*K;
    const __nv_bfloat16* Blb = Blo + ((size_t)(b*PP) + px0)*K;

    float acc[4][4][4];
    #pragma unroll
    for (int i=0;i<4;i++)
        #pragma unroll
        for (int j=0;j<4;j++)
            #pragma unroll
            for (int q=0;q<4;q++) acc[i][j][q] = 0.f;

    int l16 = lane & 15;
    uint32_t aoff_base = (uint32_t)((wm*64 + (lane & 15))*144 + ((lane >> 4) << 3)*2);
    uint32_t boff_base = (uint32_t)((wn*32 + (l16 & 7))*144 + ((l16 >> 3) << 3)*2);

    gemm_copy<K>(su, 0, 0, t, Ab, Alb, Bb, Blb);
    CP_COMMIT();

    for (int c = 0; c < CHUNKS; c++){
        CP_WAIT0();
        __syncthreads();
        if (c+1 < CHUNKS){ gemm_copy<K>(su, (c+1)&1, c+1, t, Ab, Alb, Bb, Blb); CP_COMMIT(); }
        uint32_t sb = su + (c&1)*G_STAGE;
        #pragma unroll
        for (int ks = 0; ks < 4; ks++){
            uint32_t bh[4][2], bl[4][2];
            #pragma unroll
            for (int na=0;na<4;na++){
                uint32_t boff = boff_base + (uint32_t)(na*8*144 + ks*32);
                LDSM_X2(bh[na], sb + 2*T_BYTES + boff);
                LDSM_X2(bl[na], sb + 3*T_BYTES + boff);
            }
            #pragma unroll
            for (int ma=0;ma<4;ma++){
                uint32_t aoff = aoff_base + (uint32_t)(ma*16*144 + ks*32);
                uint32_t ah[4], al[4];
                LDSM_X4(ah, sb + aoff);
                LDSM_X4(al, sb + T_BYTES + aoff);
                #pragma unroll
                for (int na=0;na<4;na++){
                    MMA16816(acc[ma][na], ah, bh[na]);
                    MMA16816(acc[ma][na], al, bh[na]);
                    MMA16816(acc[ma][na], ah, bl[na]);
                }
            }
        }
    }

    if (MODE == 2){
        #pragma unroll
        for (int ma=0;ma<4;ma++){
            int r0 = co0 + wm*64 + ma*16 + (lane>>2);
            int r1 = r0 + 8;
            float bb0 = bias[r0], bb1 = bias[r1];
            float iv0 = gamma[r0]*rsqrtf(var[r0]+1e-5f), sh0 = beta[r0]-mean[r0]*iv0;
            float iv1 = gamma[r1]*rsqrtf(var[r1]+1e-5f), sh1 = beta[r1]-mean[r1]*iv1;
            #pragma unroll
            for (int na=0;na<4;na++){
                int px = px0 + wn*32 + na*8 + ((lane&3)<<1);
                size_t i0 = ((size_t)(b*CC + r0))*PP + px;
                size_t i1 = ((size_t)(b*CC + r1))*PP + px;
                float2 rv0 = *(const float2*)&resid[i0];
                float2 rv1 = *(const float2*)&resid[i1];
                float v0 = (acc[ma][na][0]+bb0)*iv0 + sh0;
                float v1 = (acc[ma][na][1]+bb0)*iv0 + sh0;
                float v2 = (acc[ma][na][2]+bb1)*iv1 + sh1;
                float v3 = (acc[ma][na][3]+bb1)*iv1 + sh1;
                *(float2*)&outp[i0] = make_float2(rv0.x + v0*sigm(v0), rv0.y + v1*sigm(v1));
                *(float2*)&outp[i1] = make_float2(rv1.x + v2*sigm(v2), rv1.y + v3*sigm(v3));
            }
        }
        return;
    }

    __syncthreads();
    #pragma unroll
    for (int ma=0;ma<4;ma++){
        int r0 = wm*64 + ma*16 + (lane>>2);
        int r1 = r0 + 8;
        int gr0 = co0 + r0, gr1 = co0 + r1;
        float bb0=0.f, bb1=0.f;
        if (MODE==1){ bb0 = bias[gr0]; bb1 = bias[gr1]; }
        #pragma unroll
        for (int na=0;na<4;na++){
            int px = wn*32 + na*8 + ((lane&3)<<1);
            float d0 = acc[ma][na][0], d1 = acc[ma][na][1];
            float d2 = acc[ma][na][2], d3 = acc[ma][na][3];
            float v0, v1, v2, v3;
            if (MODE==0){
                size_t i0 = ((size_t)(b*CC + gr0))*PP + px0 + px;
                size_t i1 = ((size_t)(b*CC + gr1))*PP + px0 + px;
                *(float2*)&g_xdense[i0] = make_float2(d0, d1);
                *(float2*)&g_xdense[i1] = make_float2(d2, d3);
                v0 = d0; v1 = d1; v2 = d2; v3 = d3;
            } else {
                size_t i0 = ((size_t)(b*CC + gr0))*PP + px0 + px;
                size_t i1 = ((size_t)(b*CC + gr1))*PP + px0 + px;
                float2 x0 = *(const float2*)&g_xdense[i0];
                float2 x1 = *(const float2*)&g_xdense[i1];
                v0 = x0.x * sigm(d0+bb0);
                v1 = x0.y * sigm(d1+bb0);
                v2 = x1.x * sigm(d2+bb1);
                v3 = x1.y * sigm(d3+bb1);
            }
            __nv_bfloat16 h,l;
            split2(v0,h,l);
            *(__nv_bfloat16*)(smem + px*272 + r0*2) = h;
            *(__nv_bfloat16*)(smem + 34816 + px*272 + r0*2) = l;
            split2(v1,h,l);
            *(__nv_bfloat16*)(smem + (px+1)*272 + r0*2) = h;
            *(__nv_bfloat16*)(smem + 34816 + (px+1)*272 + r0*2) = l;
            split2(v2,h,l);
            *(__nv_bfloat16*)(smem + px*272 + r1*2) = h;
            *(__nv_bfloat16*)(smem + 34816 + px*272 + r1*2) = l;
            split2(v3,h,l);
            *(__nv_bfloat16*)(smem + (px+1)*272 + r1*2) = h;
            *(__nv_bfloat16*)(smem + 34816 + (px+1)*272 + r1*2) = l;
        }
    }
    __syncthreads();
    {
        __nv_bfloat16* Dh = (MODE==0) ? g_Bxhi : g_Bohi;
        __nv_bfloat16* Dl = (MODE==0) ? g_Bxlo : g_Bolo;
        #pragma unroll
        for (int i=0;i<8;i++){
            int e = t + i*256;
            int r = e >> 4, c16 = e & 15;
            size_t o = ((size_t)(b*PP) + px0 + r)*256 + co0 + c16*8;
            *(uint4*)(Dh + o) = *(const uint4*)(smem + r*272 + c16*16);
            *(uint4*)(Dl + o) = *(const uint4*)(smem + 34816 + r*272 + c16*16);
        }
    }
}

// ---------------- launch ----------------
extern "C" void kernel_launch(void* const* d_in, const int* in_sizes, int n_in,
                              void* d_out, int out_size){
    const float* x       = (const float*)d_in[0];
    const float* x_prev  = (const float*)d_in[1];
    const float* w_off   = (const float*)d_in[2];
    const float* b_off   = (const float*)d_in[3];
    const float* w_def   = (const float*)d_in[4];
    const float* w_cross = (const float*)d_in[5];
    const float* w_g1    = (const float*)d_in[6];
    const float* b_g1    = (const float*)d_in[7];
    const float* g1_gamma= (const float*)d_in[8];
    const float* g1_beta = (const float*)d_in[9];
    const float* g1_mean = (const float*)d_in[10];
    const float* g1_var  = (const float*)d_in[11];
    const float* w_g2    = (const float*)d_in[12];
    const float* b_g2    = (const float*)d_in[13];
    const float* w_out   = (const float*)d_in[14];
    const float* b_out   = (const float*)d_in[15];
    const float* o_gamma = (const float*)d_in[16];
    const float* o_beta  = (const float*)d_in[17];
    const float* o_mean  = (const float*)d_in[18];
    const float* o_var   = (const float*)d_in[19];
    float* out = (float*)d_out;

    cudaFuncSetAttribute(gemm_mma<0>, cudaFuncAttributeMaxDynamicSharedMemorySize, SMEM_GEMM);
    cudaFuncSetAttribute(gemm_mma<1>, cudaFuncAttributeMaxDynamicSharedMemorySize, SMEM_GEMM);
    cudaFuncSetAttribute(gemm_mma<2>, cudaFuncAttributeMaxDynamicSharedMemorySize, SMEM_GEMM);
    cudaFuncSetAttribute(deform_mma,  cudaFuncAttributeMaxDynamicSharedMemorySize, DSM_TOTAL);
    cudaFuncSetAttribute((void*)conv3_mma<32,0>, cudaFuncAttributeMaxDynamicSharedMemorySize, OFFC_SMEM);
    cudaFuncSetAttribute((void*)conv3_mma<64,1>, cudaFuncAttributeMaxDynamicSharedMemorySize, G1C_SMEM);

    split_all<<<2272, 256>>>(w_cross, w_g2, w_out, w_def, w_g1, w_off);
    conv_rows<0><<<dim3(PP/32, 8, BB), 256>>>(x);
    conv_rows<1><<<dim3(PP/32, 8, BB), 256>>>(x_prev);

    conv3_mma<32,0><<<dim3(PP/128, BB), 256, OFFC_SMEM>>>(b_off, nullptr, nullptr, nullptr, nullptr);
    deform_mma<<<dim3(PP/128, GG, BB), 256, DSM_TOTAL>>>(x);

    gemm_mma<0><<<dim3(PP/128, 2, BB), 256, SMEM_GEMM>>>(nullptr,nullptr,nullptr,nullptr,nullptr,nullptr,nullptr);
    conv3_mma<64,1><<<dim3(PP/128, BB), 256, G1C_SMEM>>>(b_g1, g1_gamma, g1_beta, g1_mean, g1_var);
    gemm_mma<1><<<dim3(PP/128, 2, BB), 256, SMEM_GEMM>>>(b_g2,nullptr,nullptr,nullptr,nullptr,nullptr,nullptr);
    gemm_mma<2><<<dim3(PP/128, 2, BB), 256, SMEM_GEMM>>>(b_out, o_gamma, o_beta, o_mean, o_var, x, out);
}